// round 12
// baseline (speedup 1.0000x reference)
#include <cuda_runtime.h>
#include <cuda_bf16.h>
#include <math.h>

#define NNODES 8192
#define KNBR   32

// ---------------- scratch (static device arrays; no allocation) ----------------
__device__ __align__(16) float g_proj  [NNODES * 1152];   // q(192)|kv(384)|qp(144)|kvp(432)
__device__ __align__(16) float g_bcat  [1152];
__device__ __align__(16) float g_qpts  [NNODES * 144];
__device__ __align__(16) float g_kvpts [NNODES * 432];
__device__ __align__(16) float g_bpairT[NNODES * 384];        // [n][h][k] transposed, coalesced read
__device__ __align__(16) float g_pairz [NNODES * KNBR * 32];
__device__ __align__(16) float g_attn  [NNODES * 12 * 32];    // per (node,head) 128B line: k[16]|kpts[12]|pad
__device__ __align__(16) __nv_bfloat16 g_sh   [NNODES * 384];
__device__ __align__(16) __nv_bfloat16 g_sl   [NNODES * 384];
__device__ __align__(16) __nv_bfloat16 g_wcath[384 * 1152];
__device__ __align__(16) __nv_bfloat16 g_wcatl[384 * 1152];
__device__ __align__(16) __nv_bfloat16 g_wouth[960 * 384];
__device__ __align__(16) __nv_bfloat16 g_woutl[960 * 384];
__device__ __align__(16) __nv_bfloat16 g_cath [NNODES * 960];
__device__ __align__(16) __nv_bfloat16 g_catl [NNODES * 960];
__device__ __align__(16) __nv_bfloat16 g_zwh  [128 * 64];
__device__ __align__(16) __nv_bfloat16 g_zwl  [128 * 64];

// ---------------- helpers ----------------
__device__ __forceinline__ void split_store(__nv_bfloat16* ph, __nv_bfloat16* pl, float x)
{
    __nv_bfloat16 h = __float2bfloat16(x);
    *ph = h;
    *pl = __float2bfloat16(x - __bfloat162float(h));
}

__device__ __forceinline__ void mma_bf16(float* c, const unsigned* a, const unsigned* b)
{
    asm volatile(
        "mma.sync.aligned.m16n8k16.row.col.f32.bf16.bf16.f32 "
        "{%0,%1,%2,%3}, {%4,%5,%6,%7}, {%8,%9}, {%0,%1,%2,%3};"
        : "+f"(c[0]), "+f"(c[1]), "+f"(c[2]), "+f"(c[3])
        : "r"(a[0]), "r"(a[1]), "r"(a[2]), "r"(a[3]), "r"(b[0]), "r"(b[1]));
}
__device__ __forceinline__ void ldsm_x4(unsigned* d, unsigned addr)
{
    asm volatile("ldmatrix.sync.aligned.m8n8.x4.shared.b16 {%0,%1,%2,%3}, [%4];"
                 : "=r"(d[0]), "=r"(d[1]), "=r"(d[2]), "=r"(d[3]) : "r"(addr));
}
__device__ __forceinline__ void ldsm_x2t(unsigned* d, unsigned addr)
{
    asm volatile("ldmatrix.sync.aligned.m8n8.x2.trans.shared.b16 {%0,%1}, [%2];"
                 : "=r"(d[0]), "=r"(d[1]) : "r"(addr));
}

// ---------------- prep_all ----------------
__global__ void prep_all(const float4* __restrict__ s,
                         const float* __restrict__ wq, const float* __restrict__ wkv,
                         const float* __restrict__ wqp, const float* __restrict__ wkvp,
                         const float* __restrict__ bq, const float* __restrict__ bkv,
                         const float* __restrict__ bqp, const float* __restrict__ bkvp,
                         const float* __restrict__ wout,
                         const float* __restrict__ wb, const float* __restrict__ wdz)
{
    const int t  = blockIdx.x * blockDim.x + threadIdx.x;
    const int st = gridDim.x * blockDim.x;
    for (int i = t; i < NNODES * 384 / 4; i += st) {
        float4 v = s[i];
        __nv_bfloat16* ph = g_sh + i * 4;
        __nv_bfloat16* pl = g_sl + i * 4;
        split_store(ph + 0, pl + 0, v.x);
        split_store(ph + 1, pl + 1, v.y);
        split_store(ph + 2, pl + 2, v.z);
        split_store(ph + 3, pl + 3, v.w);
    }
    for (int i = t; i < 384 * 1152; i += st) {
        int r = i / 1152, c = i % 1152;
        float v;
        if      (c < 192) v = wq  [r * 192 + c];
        else if (c < 576) v = wkv [r * 384 + (c - 192)];
        else if (c < 720) v = wqp [r * 144 + (c - 576)];
        else              v = wkvp[r * 432 + (c - 720)];
        split_store(g_wcath + i, g_wcatl + i, v);
    }
    for (int i = t; i < 960 * 384; i += st)
        split_store(g_wouth + i, g_woutl + i, wout[i]);
    for (int i = t; i < 128 * 64; i += st) {
        int r = i >> 6, c = i & 63;
        float v = 0.f;
        if      (c < 12) v = wb [r * 12 + c];
        else if (c < 44) v = wdz[r * 32 + (c - 12)];
        split_store(g_zwh + i, g_zwl + i, v);
    }
    for (int i = t; i < 1152; i += st) {
        float v;
        if      (i < 192) v = bq [i];
        else if (i < 576) v = bkv[i - 192];
        else if (i < 720) v = bqp[i - 576];
        else              v = bkvp[i - 720];
        g_bcat[i] = v;
    }
}

// ---------------- bf16 hi/lo compensated tensor-core GEMM ----------------
#define BM 128
#define BN 64
#define KC 32
template<int K>
__device__ __forceinline__ void mma_gemm_body(
    const __nv_bfloat16* __restrict__ Ah, const __nv_bfloat16* __restrict__ Al,
    const __nv_bfloat16* __restrict__ Bh, const __nv_bfloat16* __restrict__ Bl,
    const float* __restrict__ bias, float* __restrict__ C, const int N)
{
    __shared__ __nv_bfloat16 sAh[BM * 40], sAl[BM * 40];
    __shared__ __nv_bfloat16 sBh[KC * 72], sBl[KC * 72];

    const int tid  = threadIdx.x;
    const int lane = tid & 31, warp = tid >> 5;
    const int wm = warp >> 2, wn = warp & 3;
    const long brow = (long)blockIdx.y * BM;
    const long bcol = (long)blockIdx.x * BN;

    float acc[4][2][4];
#pragma unroll
    for (int mi = 0; mi < 4; mi++)
#pragma unroll
        for (int ni = 0; ni < 2; ni++)
#pragma unroll
            for (int r = 0; r < 4; r++) acc[mi][ni][r] = 0.f;

    const int arow  = tid >> 1, apart = (tid & 1) * 16;
    const int bkr   = tid >> 3, bnp   = (tid & 7) * 8;

    const unsigned sAh_u = (unsigned)__cvta_generic_to_shared(sAh);
    const unsigned sAl_u = (unsigned)__cvta_generic_to_shared(sAl);
    const unsigned sBh_u = (unsigned)__cvta_generic_to_shared(sBh);
    const unsigned sBl_u = (unsigned)__cvta_generic_to_shared(sBl);

    uint4 rah0, rah1, ral0, ral1, rbh, rbl;
    {
        const size_t aoff = (size_t)(brow + arow) * K + apart;
        rah0 = *(const uint4*)(Ah + aoff); rah1 = *(const uint4*)(Ah + aoff + 8);
        ral0 = *(const uint4*)(Al + aoff); ral1 = *(const uint4*)(Al + aoff + 8);
        const size_t boff = (size_t)bkr * N + bcol + bnp;
        rbh = *(const uint4*)(Bh + boff);
        rbl = *(const uint4*)(Bl + boff);
    }

    for (int kc = 0; kc < K; kc += KC) {
        *(uint4*)(sAh + arow * 40 + apart)     = rah0;
        *(uint4*)(sAh + arow * 40 + apart + 8) = rah1;
        *(uint4*)(sAl + arow * 40 + apart)     = ral0;
        *(uint4*)(sAl + arow * 40 + apart + 8) = ral1;
        *(uint4*)(sBh + bkr * 72 + bnp) = rbh;
        *(uint4*)(sBl + bkr * 72 + bnp) = rbl;
        __syncthreads();

        const bool more = (kc + KC) < K;
        if (more) {
            const size_t aoff = (size_t)(brow + arow) * K + kc + KC + apart;
            rah0 = *(const uint4*)(Ah + aoff); rah1 = *(const uint4*)(Ah + aoff + 8);
            ral0 = *(const uint4*)(Al + aoff); ral1 = *(const uint4*)(Al + aoff + 8);
            const size_t boff = (size_t)(kc + KC + bkr) * N + bcol + bnp;
            rbh = *(const uint4*)(Bh + boff);
            rbl = *(const uint4*)(Bl + boff);
        }

#pragma unroll
        for (int ks = 0; ks < 2; ks++) {
            const int kk = ks * 16;
            unsigned afh[4][4], afl[4][4];
            const int g = lane >> 3, r = lane & 7;
#pragma unroll
            for (int mi = 0; mi < 4; mi++) {
                const int row = wm * 64 + mi * 16 + (g & 1) * 8 + r;
                const int col = kk + (g >> 1) * 8;
                ldsm_x4(afh[mi], sAh_u + (unsigned)(row * 40 + col) * 2u);
                ldsm_x4(afl[mi], sAl_u + (unsigned)(row * 40 + col) * 2u);
            }
            unsigned bfh[2][2], bfl[2][2];
            const int g2 = (lane >> 3) & 1, r2 = lane & 7;
#pragma unroll
            for (int ni = 0; ni < 2; ni++) {
                const int krow = kk + g2 * 8 + r2;
                const int col  = wn * 16 + ni * 8;
                ldsm_x2t(bfh[ni], sBh_u + (unsigned)(krow * 72 + col) * 2u);
                ldsm_x2t(bfl[ni], sBl_u + (unsigned)(krow * 72 + col) * 2u);
            }
#pragma unroll
            for (int mi = 0; mi < 4; mi++)
#pragma unroll
                for (int ni = 0; ni < 2; ni++) {
                    mma_bf16(acc[mi][ni], afh[mi], bfh[ni]);
                    mma_bf16(acc[mi][ni], afh[mi], bfl[ni]);
                    mma_bf16(acc[mi][ni], afl[mi], bfh[ni]);
                }
        }
        if (more) __syncthreads();
    }

    const int gr = lane >> 2, gc = (lane & 3) * 2;
#pragma unroll
    for (int mi = 0; mi < 4; mi++) {
        const long row0 = brow + wm * 64 + mi * 16 + gr;
#pragma unroll
        for (int ni = 0; ni < 2; ni++) {
            const long col0 = bcol + wn * 16 + ni * 8 + gc;
            const float b0 = bias[col0], b1 = bias[col0 + 1];
            float2 v0 = make_float2(acc[mi][ni][0] + b0, acc[mi][ni][1] + b1);
            float2 v1 = make_float2(acc[mi][ni][2] + b0, acc[mi][ni][3] + b1);
            *(float2*)&C[row0 * N + col0]       = v0;
            *(float2*)&C[(row0 + 8) * N + col0] = v1;
        }
    }
}

__global__ __launch_bounds__(256) void gemm_proj_mma()
{
    mma_gemm_body<384>(g_sh, g_sl, g_wcath, g_wcatl, g_bcat, g_proj, 1152);
}
__global__ __launch_bounds__(256) void gemm_out_mma(const float* __restrict__ bout,
                                                    float* __restrict__ out)
{
    mma_gemm_body<960>(g_cath, g_catl, g_wouth, g_woutl, bout, out, 384);
}

// ---------------- fused: zproj_mma (blocks 0..2047) + transform+pack (rest) ----------------
#define ZBLOCKS ((NNODES * KNBR) / BM)   // 2048
__global__ __launch_bounds__(256) void zt_fused(const float* __restrict__ z,
                                                const float* __restrict__ bb,
                                                const float* __restrict__ bdz,
                                                const float* __restrict__ rot,
                                                const float* __restrict__ trans)
{
    if (blockIdx.x >= ZBLOCKS) {
        // ---- transform + g_attn pack role: one node per block ----
        const int n = blockIdx.x - ZBLOCKS;
        __shared__ float R[9], T[3];
        const int t = threadIdx.x;
        if (t < 9) R[t] = rot[n * 9 + t];
        if (t < 3) T[t] = trans[n * 3 + t];
        __syncthreads();
        if (t < 48) {
            const float* base = g_proj + (size_t)n * 1152 + 576;
            float x = base[t], y = base[48 + t], zz = base[96 + t];
            float* o = g_qpts + (size_t)n * 144 + t * 3;
            o[0] = fmaf(R[0], x, fmaf(R[1], y, fmaf(R[2], zz, T[0])));
            o[1] = fmaf(R[3], x, fmaf(R[4], y, fmaf(R[5], zz, T[1])));
            o[2] = fmaf(R[6], x, fmaf(R[7], y, fmaf(R[8], zz, T[2])));
        } else if (t < 192) {
            const int j = t - 48;                 // point j of 144; head j/12, idx j%12
            const float* base = g_proj + (size_t)n * 1152 + 720;
            float x = base[j], y = base[144 + j], zz = base[288 + j];
            float o0 = fmaf(R[0], x, fmaf(R[1], y, fmaf(R[2], zz, T[0])));
            float o1 = fmaf(R[3], x, fmaf(R[4], y, fmaf(R[5], zz, T[1])));
            float o2 = fmaf(R[6], x, fmaf(R[7], y, fmaf(R[8], zz, T[2])));
            float* o = g_kvpts + (size_t)n * 432 + j * 3;
            o[0] = o0; o[1] = o1; o[2] = o2;
            const int h = j / 12, idx = j % 12;
            if (idx < 4) {                        // k_pts -> g_attn line slots 16..27
                float* a = g_attn + ((size_t)n * 12 + h) * 32 + 16 + idx * 3;
                a[0] = o0; a[1] = o1; a[2] = o2;
            }
        } else {
            // copy k-part into g_attn line slots 0..15
            // FIX: kv layout is k[16]|v[16] per head (stride 32); source offset
            // for flat c = h*16+c16 is 192 + h*32 + c16.
            for (int c = t - 192; c < 192; c += 64)
                g_attn[((size_t)n * 12 + (c >> 4)) * 32 + (c & 15)] =
                    g_proj[(size_t)n * 1152 + 192 + (c >> 4) * 32 + (c & 15)];
        }
        return;
    }

    // ---- zproj role ----
    __shared__ __nv_bfloat16 sAh[BM * 40], sAl[BM * 40];
    __shared__ __nv_bfloat16 sBh[KC * 72], sBl[KC * 72];

    const int tid  = threadIdx.x;
    const int lane = tid & 31, warp = tid >> 5;
    const int wm = warp >> 2, wn = warp & 3;
    const long brow = (long)blockIdx.x * BM;

    float acc[4][2][4];
#pragma unroll
    for (int mi = 0; mi < 4; mi++)
#pragma unroll
        for (int ni = 0; ni < 2; ni++)
#pragma unroll
            for (int r = 0; r < 4; r++) acc[mi][ni][r] = 0.f;

    const int arow  = tid >> 1, apart = (tid & 1) * 16;
    const int bkr   = tid >> 3, bnp   = (tid & 7) * 8;

    const unsigned sAh_u = (unsigned)__cvta_generic_to_shared(sAh);
    const unsigned sAl_u = (unsigned)__cvta_generic_to_shared(sAl);
    const unsigned sBh_u = (unsigned)__cvta_generic_to_shared(sBh);
    const unsigned sBl_u = (unsigned)__cvta_generic_to_shared(sBl);

    float4 ra[4];
    uint4 rbh, rbl;
    {
        const float* ap = z + (size_t)(brow + arow) * 128 + apart;
#pragma unroll
        for (int j = 0; j < 4; j++) ra[j] = *(const float4*)(ap + j * 4);
        rbh = *(const uint4*)(g_zwh + bkr * 64 + bnp);
        rbl = *(const uint4*)(g_zwl + bkr * 64 + bnp);
    }

    for (int kc = 0; kc < 128; kc += KC) {
        __nv_bfloat16 hh[16], ll[16];
#pragma unroll
        for (int j = 0; j < 4; j++) {
            float v[4] = {ra[j].x, ra[j].y, ra[j].z, ra[j].w};
#pragma unroll
            for (int q = 0; q < 4; q++) {
                __nv_bfloat16 h = __float2bfloat16(v[q]);
                hh[j * 4 + q] = h;
                ll[j * 4 + q] = __float2bfloat16(v[q] - __bfloat162float(h));
            }
        }
        *(uint4*)(sAh + arow * 40 + apart)     = *(uint4*)hh;
        *(uint4*)(sAh + arow * 40 + apart + 8) = *(uint4*)(hh + 8);
        *(uint4*)(sAl + arow * 40 + apart)     = *(uint4*)ll;
        *(uint4*)(sAl + arow * 40 + apart + 8) = *(uint4*)(ll + 8);
        *(uint4*)(sBh + bkr * 72 + bnp) = rbh;
        *(uint4*)(sBl + bkr * 72 + bnp) = rbl;
        __syncthreads();

        const bool more = (kc + KC) < 128;
        if (more) {
            const float* ap = z + (size_t)(brow + arow) * 128 + kc + KC + apart;
#pragma unroll
            for (int j = 0; j < 4; j++) ra[j] = *(const float4*)(ap + j * 4);
            rbh = *(const uint4*)(g_zwh + (kc + KC + bkr) * 64 + bnp);
            rbl = *(const uint4*)(g_zwl + (kc + KC + bkr) * 64 + bnp);
        }

#pragma unroll
        for (int ks = 0; ks < 2; ks++) {
            const int kk = ks * 16;
            unsigned afh[4][4], afl[4][4];
            const int g = lane >> 3, r = lane & 7;
#pragma unroll
            for (int mi = 0; mi < 4; mi++) {
                const int row = wm * 64 + mi * 16 + (g & 1) * 8 + r;
                const int col = kk + (g >> 1) * 8;
                ldsm_x4(afh[mi], sAh_u + (unsigned)(row * 40 + col) * 2u);
                ldsm_x4(afl[mi], sAl_u + (unsigned)(row * 40 + col) * 2u);
            }
            unsigned bfh[2][2], bfl[2][2];
            const int g2 = (lane >> 3) & 1, r2 = lane & 7;
#pragma unroll
            for (int ni = 0; ni < 2; ni++) {
                const int krow = kk + g2 * 8 + r2;
                const int col  = wn * 16 + ni * 8;
                ldsm_x2t(bfh[ni], sBh_u + (unsigned)(krow * 72 + col) * 2u);
                ldsm_x2t(bfl[ni], sBl_u + (unsigned)(krow * 72 + col) * 2u);
            }
#pragma unroll
            for (int mi = 0; mi < 4; mi++)
#pragma unroll
                for (int ni = 0; ni < 2; ni++) {
                    mma_bf16(acc[mi][ni], afh[mi], bfh[ni]);
                    mma_bf16(acc[mi][ni], afh[mi], bfl[ni]);
                    mma_bf16(acc[mi][ni], afl[mi], bfh[ni]);
                }
        }
        if (more) __syncthreads();
    }

    const float S = 0.5773502691896258f;
    const int gr = lane >> 2, gc = (lane & 3) * 2;
#pragma unroll
    for (int mi = 0; mi < 4; mi++) {
        const long e0 = brow + wm * 64 + mi * 16 + gr;
#pragma unroll
        for (int ni = 0; ni < 2; ni++) {
            const int colb = wn * 16 + ni * 8 + gc;
#pragma unroll
            for (int r = 0; r < 4; r++) {
                const long e   = e0 + (r >> 1) * 8;
                const int  col = colb + (r & 1);
                const float v = acc[mi][ni][r];
                if (col < 12)   // transposed: [n][h][k], n=e>>5, k=e&31
                    g_bpairT[(e >> 5) * 384 + col * 32 + (e & 31)] = S * (v + __ldg(bb + col));
                else if (col < 44)
                    g_pairz[e * 32 + (col - 12)] = v + __ldg(bdz + (col - 12));
            }
        }
    }
}

// ---------------- fused attention: cooperative coalesced logits ----------------
__device__ __forceinline__ void put_cat(size_t n, int idx, float v)
{
    split_store(g_cath + n * 960 + idx, g_catl + n * 960 + idx, v);
}

__global__ __launch_bounds__(384) void attn_kernel(const int* __restrict__ edge_index,
                                                   const float* __restrict__ rot,
                                                   const float* __restrict__ trans,
                                                   const float* __restrict__ mask,
                                                   const float* __restrict__ head_weights)
{
    int n = blockIdx.x;
    int t = threadIdx.x;
    __shared__ int   s_idx[32];
    __shared__ float s_mask[32];
    __shared__ float s_q[192];
    __shared__ float s_qp[144];
    __shared__ float s_R[9], s_T[3];
    __shared__ float s_hw[12];
    __shared__ float s_a[12][33];
    __shared__ float s_opt[288];
    __shared__ float s_pz[32][33];

    if (t < 32) {
        int nb = edge_index[n * 32 + t];
        s_idx[t]  = nb;
        s_mask[t] = mask[nb];
    }
    if (t >= 32 && t < 224)  s_q [t - 32]  = g_proj[(size_t)n * 1152 + (t - 32)];
    if (t >= 224 && t < 368) s_qp[t - 224] = g_qpts[(size_t)n * 144 + (t - 224)];
    if (t >= 368 && t < 377) s_R [t - 368] = rot  [n * 9 + (t - 368)];
    if (t >= 377 && t < 380) s_T [t - 377] = trans[n * 3 + (t - 377)];
    if (t < 12) {
        float x = head_weights[t];
        float sp = (x > 20.f) ? x : log1pf(expf(x));
        s_hw[t] = sp * 0.13608276348795434f;   // softplus * sqrt(1/54)
    }
    __syncthreads();

    // logits: warp h; all 32 lanes cooperatively process one neighbor per iteration.
    // g_attn line (nb,h): [0..15] k, [16..27] kpts, [28..31] pad.
    {
        const int h = t >> 5, lane = t & 31;
        float myq  = (lane < 16) ? s_q[h * 16 + lane] * 0.14433756729740643f : 0.f;
        float myqp = (lane >= 16 && lane < 28) ? s_qp[h * 12 + (lane - 16)] : 0.f;
        const float nhw = -0.5f * s_hw[h];
        const float* ab = g_attn + h * 32 + lane;
        float logit = 0.f;
#pragma unroll 8
        for (int k = 0; k < 32; k++) {
            float v = ab[(size_t)s_idx[k] * 384];
            float contrib;
            if (lane < 16)      contrib = myq * v;
            else if (lane < 28) { float d = myqp - v; contrib = nhw * d * d; }
            else                contrib = 0.f;
#pragma unroll
            for (int o = 16; o; o >>= 1)
                contrib += __shfl_xor_sync(0xffffffffu, contrib, o);
            if (k == lane) logit = contrib;
        }
        logit += g_bpairT[(size_t)n * 384 + h * 32 + lane]
               + 100000.0f * (s_mask[lane] - 1.0f);
        float m = logit;
#pragma unroll
        for (int o = 16; o; o >>= 1) m = fmaxf(m, __shfl_xor_sync(0xffffffffu, m, o));
        float e = expf(logit - m);
        float ssum = e;
#pragma unroll
        for (int o = 16; o; o >>= 1) ssum += __shfl_xor_sync(0xffffffffu, ssum, o);
        s_a[h][lane] = e / ssum;
    }
    for (int i = t; i < 32 * 32; i += 384)
        s_pz[i >> 5][i & 31] = g_pairz[((size_t)n * 32 + (i >> 5)) * 32 + (i & 31)];
    __syncthreads();

    // o: scalar part, 192 outputs (coalesced across lanes)
    if (t < 192) {
        int h = t >> 4, c = t & 15;
        float acc = 0.f;
#pragma unroll 4
        for (int k = 0; k < 32; k++)
            acc = fmaf(s_a[h][k], g_proj[(size_t)s_idx[k] * 1152 + 192 + h * 32 + 16 + c], acc);
        put_cat(n, h * 16 + c, acc);
    }
    // o_pt: 288 outputs
    if (t < 288) {
        int j = t / 3, i = t - j * 3;
        int h = j >> 3, p = j & 7;
        float acc = 0.f;
#pragma unroll 4
        for (int k = 0; k < 32; k++)
            acc = fmaf(s_a[h][k], g_kvpts[(size_t)s_idx[k] * 432 + h * 36 + (4 + p) * 3 + i], acc);
        s_opt[t] = acc;
    }
    // o_pair: smem-resident
    {
        int h = t >> 5, c = t & 31;
        float acc = 0.f;
#pragma unroll
        for (int k = 0; k < 32; k++)
            acc = fmaf(s_a[h][k], s_pz[k][c], acc);
        put_cat(n, 576 + h * 32 + c, acc);
    }
    __syncthreads();
    if (t < 96) {
        float gx = s_opt[t * 3 + 0] - s_T[0];
        float gy = s_opt[t * 3 + 1] - s_T[1];
        float gz = s_opt[t * 3 + 2] - s_T[2];
        float lx = fmaf(s_R[0], gx, fmaf(s_R[3], gy, s_R[6] * gz));
        float ly = fmaf(s_R[1], gx, fmaf(s_R[4], gy, s_R[7] * gz));
        float lz = fmaf(s_R[2], gx, fmaf(s_R[5], gy, s_R[8] * gz));
        put_cat(n, 192 + t, lx);
        put_cat(n, 288 + t, ly);
        put_cat(n, 384 + t, lz);
        put_cat(n, 480 + t, sqrtf(fmaf(lx, lx, fmaf(ly, ly, fmaf(lz, lz, 1e-8f)))));
    }
}

// ---------------- launch: prep(1) gemm_proj(2) zt(3) attn(4=profiled) gemm_out(5) ----------------
extern "C" void kernel_launch(void* const* d_in, const int* in_sizes, int n_in,
                              void* d_out, int out_size)
{
    const float* s     = (const float*)d_in[0];
    const float* z     = (const float*)d_in[1];
    const int*   ei    = (const int*)  d_in[2];
    const float* rot   = (const float*)d_in[3];
    const float* trans = (const float*)d_in[4];
    const float* mask  = (const float*)d_in[5];
    const float* w_q   = (const float*)d_in[6];
    const float* b_q   = (const float*)d_in[7];
    const float* w_kv  = (const float*)d_in[8];
    const float* b_kv  = (const float*)d_in[9];
    const float* w_qp  = (const float*)d_in[10];
    const float* b_qp  = (const float*)d_in[11];
    const float* w_kvp = (const float*)d_in[12];
    const float* b_kvp = (const float*)d_in[13];
    const float* w_b   = (const float*)d_in[14];
    const float* b_b   = (const float*)d_in[15];
    const float* w_dz  = (const float*)d_in[16];
    const float* b_dz  = (const float*)d_in[17];
    const float* hw    = (const float*)d_in[18];
    const float* w_out = (const float*)d_in[19];
    const float* b_out = (const float*)d_in[20];
    float* out = (float*)d_out;

    prep_all<<<512, 256>>>((const float4*)s, w_q, w_kv, w_qp, w_kvp,
                           b_q, b_kv, b_qp, b_kvp, w_out, w_b, w_dz);        // slot 1
    gemm_proj_mma<<<dim3(1152 / BN, NNODES / BM), 256>>>();                  // slot 2
    zt_fused<<<ZBLOCKS + NNODES, 256>>>(z, b_b, b_dz, rot, trans);           // slot 3
    attn_kernel<<<NNODES, 384>>>(ei, rot, trans, mask, hw);                  // slot 4 (profiled)
    gemm_out_mma<<<dim3(384 / BN, NNODES / BM), 256>>>(b_out, out);          // slot 5
}

// round 13
// speedup vs baseline: 1.0074x; 1.0074x over previous
#include <cuda_runtime.h>
#include <cuda_bf16.h>
#include <math.h>

#define NNODES 8192
#define KNBR   32

// ---------------- scratch (static device arrays; no allocation) ----------------
__device__ __align__(16) float g_proj  [NNODES * 1152];   // q(192)|kv(384)|qp(144)|kvp(432)
__device__ __align__(16) float g_bcat  [1152];
__device__ __align__(16) float g_qpts  [NNODES * 144];
__device__ __align__(16) float g_kvpts [NNODES * 432];
__device__ __align__(16) float g_bpairT[NNODES * 384];        // [n][h][k] transposed
__device__ __align__(16) float g_pairz [NNODES * KNBR * 32];
__device__ __align__(16) float g_attn  [NNODES * 12 * 32];    // (node,head) 128B line: k[16]|kpts[12]|pad
__device__ __align__(16) __nv_bfloat16 g_sh   [NNODES * 384];
__device__ __align__(16) __nv_bfloat16 g_sl   [NNODES * 384];
__device__ __align__(16) __nv_bfloat16 g_wcath[384 * 1152];
__device__ __align__(16) __nv_bfloat16 g_wcatl[384 * 1152];
__device__ __align__(16) __nv_bfloat16 g_wouth[960 * 384];
__device__ __align__(16) __nv_bfloat16 g_woutl[960 * 384];
__device__ __align__(16) __nv_bfloat16 g_cath [NNODES * 960];
__device__ __align__(16) __nv_bfloat16 g_catl [NNODES * 960];
__device__ __align__(16) __nv_bfloat16 g_zwh  [128 * 64];
__device__ __align__(16) __nv_bfloat16 g_zwl  [128 * 64];

// ---------------- helpers ----------------
__device__ __forceinline__ void split_store(__nv_bfloat16* ph, __nv_bfloat16* pl, float x)
{
    __nv_bfloat16 h = __float2bfloat16(x);
    *ph = h;
    *pl = __float2bfloat16(x - __bfloat162float(h));
}

__device__ __forceinline__ void mma_bf16(float* c, const unsigned* a, const unsigned* b)
{
    asm volatile(
        "mma.sync.aligned.m16n8k16.row.col.f32.bf16.bf16.f32 "
        "{%0,%1,%2,%3}, {%4,%5,%6,%7}, {%8,%9}, {%0,%1,%2,%3};"
        : "+f"(c[0]), "+f"(c[1]), "+f"(c[2]), "+f"(c[3])
        : "r"(a[0]), "r"(a[1]), "r"(a[2]), "r"(a[3]), "r"(b[0]), "r"(b[1]));
}
__device__ __forceinline__ void ldsm_x4(unsigned* d, unsigned addr)
{
    asm volatile("ldmatrix.sync.aligned.m8n8.x4.shared.b16 {%0,%1,%2,%3}, [%4];"
                 : "=r"(d[0]), "=r"(d[1]), "=r"(d[2]), "=r"(d[3]) : "r"(addr));
}
__device__ __forceinline__ void ldsm_x2t(unsigned* d, unsigned addr)
{
    asm volatile("ldmatrix.sync.aligned.m8n8.x2.trans.shared.b16 {%0,%1}, [%2];"
                 : "=r"(d[0]), "=r"(d[1]) : "r"(addr));
}

// ---------------- prep_all ----------------
__global__ void prep_all(const float4* __restrict__ s,
                         const float* __restrict__ wq, const float* __restrict__ wkv,
                         const float* __restrict__ wqp, const float* __restrict__ wkvp,
                         const float* __restrict__ bq, const float* __restrict__ bkv,
                         const float* __restrict__ bqp, const float* __restrict__ bkvp,
                         const float* __restrict__ wout,
                         const float* __restrict__ wb, const float* __restrict__ wdz)
{
    const int t  = blockIdx.x * blockDim.x + threadIdx.x;
    const int st = gridDim.x * blockDim.x;
    for (int i = t; i < NNODES * 384 / 4; i += st) {
        float4 v = s[i];
        __nv_bfloat16* ph = g_sh + i * 4;
        __nv_bfloat16* pl = g_sl + i * 4;
        split_store(ph + 0, pl + 0, v.x);
        split_store(ph + 1, pl + 1, v.y);
        split_store(ph + 2, pl + 2, v.z);
        split_store(ph + 3, pl + 3, v.w);
    }
    for (int i = t; i < 384 * 1152; i += st) {
        int r = i / 1152, c = i % 1152;
        float v;
        if      (c < 192) v = wq  [r * 192 + c];
        else if (c < 576) v = wkv [r * 384 + (c - 192)];
        else if (c < 720) v = wqp [r * 144 + (c - 576)];
        else              v = wkvp[r * 432 + (c - 720)];
        split_store(g_wcath + i, g_wcatl + i, v);
    }
    for (int i = t; i < 960 * 384; i += st)
        split_store(g_wouth + i, g_woutl + i, wout[i]);
    for (int i = t; i < 128 * 64; i += st) {
        int r = i >> 6, c = i & 63;
        float v = 0.f;
        if      (c < 12) v = wb [r * 12 + c];
        else if (c < 44) v = wdz[r * 32 + (c - 12)];
        split_store(g_zwh + i, g_zwl + i, v);
    }
    for (int i = t; i < 1152; i += st) {
        float v;
        if      (i < 192) v = bq [i];
        else if (i < 576) v = bkv[i - 192];
        else if (i < 720) v = bqp[i - 576];
        else              v = bkvp[i - 720];
        g_bcat[i] = v;
    }
}

// ---------------- bf16 hi/lo compensated tensor-core GEMM ----------------
#define BM 128
#define BN 64
#define KC 32
template<int K>
__device__ __forceinline__ void mma_gemm_body(
    const __nv_bfloat16* __restrict__ Ah, const __nv_bfloat16* __restrict__ Al,
    const __nv_bfloat16* __restrict__ Bh, const __nv_bfloat16* __restrict__ Bl,
    const float* __restrict__ bias, float* __restrict__ C, const int N)
{
    __shared__ __nv_bfloat16 sAh[BM * 40], sAl[BM * 40];
    __shared__ __nv_bfloat16 sBh[KC * 72], sBl[KC * 72];

    const int tid  = threadIdx.x;
    const int lane = tid & 31, warp = tid >> 5;
    const int wm = warp >> 2, wn = warp & 3;
    const long brow = (long)blockIdx.y * BM;
    const long bcol = (long)blockIdx.x * BN;

    float acc[4][2][4];
#pragma unroll
    for (int mi = 0; mi < 4; mi++)
#pragma unroll
        for (int ni = 0; ni < 2; ni++)
#pragma unroll
            for (int r = 0; r < 4; r++) acc[mi][ni][r] = 0.f;

    const int arow  = tid >> 1, apart = (tid & 1) * 16;
    const int bkr   = tid >> 3, bnp   = (tid & 7) * 8;

    const unsigned sAh_u = (unsigned)__cvta_generic_to_shared(sAh);
    const unsigned sAl_u = (unsigned)__cvta_generic_to_shared(sAl);
    const unsigned sBh_u = (unsigned)__cvta_generic_to_shared(sBh);
    const unsigned sBl_u = (unsigned)__cvta_generic_to_shared(sBl);

    uint4 rah0, rah1, ral0, ral1, rbh, rbl;
    {
        const size_t aoff = (size_t)(brow + arow) * K + apart;
        rah0 = *(const uint4*)(Ah + aoff); rah1 = *(const uint4*)(Ah + aoff + 8);
        ral0 = *(const uint4*)(Al + aoff); ral1 = *(const uint4*)(Al + aoff + 8);
        const size_t boff = (size_t)bkr * N + bcol + bnp;
        rbh = *(const uint4*)(Bh + boff);
        rbl = *(const uint4*)(Bl + boff);
    }

    for (int kc = 0; kc < K; kc += KC) {
        *(uint4*)(sAh + arow * 40 + apart)     = rah0;
        *(uint4*)(sAh + arow * 40 + apart + 8) = rah1;
        *(uint4*)(sAl + arow * 40 + apart)     = ral0;
        *(uint4*)(sAl + arow * 40 + apart + 8) = ral1;
        *(uint4*)(sBh + bkr * 72 + bnp) = rbh;
        *(uint4*)(sBl + bkr * 72 + bnp) = rbl;
        __syncthreads();

        const bool more = (kc + KC) < K;
        if (more) {
            const size_t aoff = (size_t)(brow + arow) * K + kc + KC + apart;
            rah0 = *(const uint4*)(Ah + aoff); rah1 = *(const uint4*)(Ah + aoff + 8);
            ral0 = *(const uint4*)(Al + aoff); ral1 = *(const uint4*)(Al + aoff + 8);
            const size_t boff = (size_t)(kc + KC + bkr) * N + bcol + bnp;
            rbh = *(const uint4*)(Bh + boff);
            rbl = *(const uint4*)(Bl + boff);
        }

#pragma unroll
        for (int ks = 0; ks < 2; ks++) {
            const int kk = ks * 16;
            unsigned afh[4][4], afl[4][4];
            const int g = lane >> 3, r = lane & 7;
#pragma unroll
            for (int mi = 0; mi < 4; mi++) {
                const int row = wm * 64 + mi * 16 + (g & 1) * 8 + r;
                const int col = kk + (g >> 1) * 8;
                ldsm_x4(afh[mi], sAh_u + (unsigned)(row * 40 + col) * 2u);
                ldsm_x4(afl[mi], sAl_u + (unsigned)(row * 40 + col) * 2u);
            }
            unsigned bfh[2][2], bfl[2][2];
            const int g2 = (lane >> 3) & 1, r2 = lane & 7;
#pragma unroll
            for (int ni = 0; ni < 2; ni++) {
                const int krow = kk + g2 * 8 + r2;
                const int col  = wn * 16 + ni * 8;
                ldsm_x2t(bfh[ni], sBh_u + (unsigned)(krow * 72 + col) * 2u);
                ldsm_x2t(bfl[ni], sBl_u + (unsigned)(krow * 72 + col) * 2u);
            }
#pragma unroll
            for (int mi = 0; mi < 4; mi++)
#pragma unroll
                for (int ni = 0; ni < 2; ni++) {
                    mma_bf16(acc[mi][ni], afh[mi], bfh[ni]);
                    mma_bf16(acc[mi][ni], afh[mi], bfl[ni]);
                    mma_bf16(acc[mi][ni], afl[mi], bfh[ni]);
                }
        }
        if (more) __syncthreads();
    }

    const int gr = lane >> 2, gc = (lane & 3) * 2;
#pragma unroll
    for (int mi = 0; mi < 4; mi++) {
        const long row0 = brow + wm * 64 + mi * 16 + gr;
#pragma unroll
        for (int ni = 0; ni < 2; ni++) {
            const long col0 = bcol + wn * 16 + ni * 8 + gc;
            const float b0 = bias[col0], b1 = bias[col0 + 1];
            float2 v0 = make_float2(acc[mi][ni][0] + b0, acc[mi][ni][1] + b1);
            float2 v1 = make_float2(acc[mi][ni][2] + b0, acc[mi][ni][3] + b1);
            *(float2*)&C[row0 * N + col0]       = v0;
            *(float2*)&C[(row0 + 8) * N + col0] = v1;
        }
    }
}

__global__ __launch_bounds__(256) void gemm_proj_mma()
{
    mma_gemm_body<384>(g_sh, g_sl, g_wcath, g_wcatl, g_bcat, g_proj, 1152);
}
__global__ __launch_bounds__(256) void gemm_out_mma(const float* __restrict__ bout,
                                                    float* __restrict__ out)
{
    mma_gemm_body<960>(g_cath, g_catl, g_wouth, g_woutl, bout, out, 384);
}

// ---------------- transform + g_attn pack (separate kernel: tiny smem, high occupancy) ----------------
__global__ __launch_bounds__(256) void transform_pack(const float* __restrict__ rot,
                                                      const float* __restrict__ trans)
{
    const int n = blockIdx.x;
    __shared__ float R[9], T[3];
    const int t = threadIdx.x;
    if (t < 9) R[t] = rot[n * 9 + t];
    if (t < 3) T[t] = trans[n * 3 + t];
    __syncthreads();
    if (t < 48) {
        const float* base = g_proj + (size_t)n * 1152 + 576;
        float x = base[t], y = base[48 + t], zz = base[96 + t];
        float* o = g_qpts + (size_t)n * 144 + t * 3;
        o[0] = fmaf(R[0], x, fmaf(R[1], y, fmaf(R[2], zz, T[0])));
        o[1] = fmaf(R[3], x, fmaf(R[4], y, fmaf(R[5], zz, T[1])));
        o[2] = fmaf(R[6], x, fmaf(R[7], y, fmaf(R[8], zz, T[2])));
    } else if (t < 192) {
        const int j = t - 48;                 // point j of 144; head j/12, idx j%12
        const float* base = g_proj + (size_t)n * 1152 + 720;
        float x = base[j], y = base[144 + j], zz = base[288 + j];
        float o0 = fmaf(R[0], x, fmaf(R[1], y, fmaf(R[2], zz, T[0])));
        float o1 = fmaf(R[3], x, fmaf(R[4], y, fmaf(R[5], zz, T[1])));
        float o2 = fmaf(R[6], x, fmaf(R[7], y, fmaf(R[8], zz, T[2])));
        float* o = g_kvpts + (size_t)n * 432 + j * 3;
        o[0] = o0; o[1] = o1; o[2] = o2;
        const int h = j / 12, idx = j % 12;
        if (idx < 4) {                        // k_pts -> g_attn line slots 16..27
            float* a = g_attn + ((size_t)n * 12 + h) * 32 + 16 + idx * 3;
            a[0] = o0; a[1] = o1; a[2] = o2;
        }
    } else {
        // k-part into g_attn slots 0..15 (kv layout: k[16]|v[16] per head, stride 32)
        for (int c = t - 192; c < 192; c += 64)
            g_attn[((size_t)n * 12 + (c >> 4)) * 32 + (c & 15)] =
                g_proj[(size_t)n * 1152 + 192 + (c >> 4) * 32 + (c & 15)];
    }
}

// ---------------- zproj via tensor cores (separate kernel, grid=2048) ----------------
__global__ __launch_bounds__(256) void zproj_mma(const float* __restrict__ z,
                                                 const float* __restrict__ bb,
                                                 const float* __restrict__ bdz)
{
    __shared__ __nv_bfloat16 sAh[BM * 40], sAl[BM * 40];
    __shared__ __nv_bfloat16 sBh[KC * 72], sBl[KC * 72];

    const int tid  = threadIdx.x;
    const int lane = tid & 31, warp = tid >> 5;
    const int wm = warp >> 2, wn = warp & 3;
    const long brow = (long)blockIdx.x * BM;

    float acc[4][2][4];
#pragma unroll
    for (int mi = 0; mi < 4; mi++)
#pragma unroll
        for (int ni = 0; ni < 2; ni++)
#pragma unroll
            for (int r = 0; r < 4; r++) acc[mi][ni][r] = 0.f;

    const int arow  = tid >> 1, apart = (tid & 1) * 16;
    const int bkr   = tid >> 3, bnp   = (tid & 7) * 8;

    const unsigned sAh_u = (unsigned)__cvta_generic_to_shared(sAh);
    const unsigned sAl_u = (unsigned)__cvta_generic_to_shared(sAl);
    const unsigned sBh_u = (unsigned)__cvta_generic_to_shared(sBh);
    const unsigned sBl_u = (unsigned)__cvta_generic_to_shared(sBl);

    float4 ra[4];
    uint4 rbh, rbl;
    {
        const float* ap = z + (size_t)(brow + arow) * 128 + apart;
#pragma unroll
        for (int j = 0; j < 4; j++) ra[j] = *(const float4*)(ap + j * 4);
        rbh = *(const uint4*)(g_zwh + bkr * 64 + bnp);
        rbl = *(const uint4*)(g_zwl + bkr * 64 + bnp);
    }

    for (int kc = 0; kc < 128; kc += KC) {
        __nv_bfloat16 hh[16], ll[16];
#pragma unroll
        for (int j = 0; j < 4; j++) {
            float v[4] = {ra[j].x, ra[j].y, ra[j].z, ra[j].w};
#pragma unroll
            for (int q = 0; q < 4; q++) {
                __nv_bfloat16 h = __float2bfloat16(v[q]);
                hh[j * 4 + q] = h;
                ll[j * 4 + q] = __float2bfloat16(v[q] - __bfloat162float(h));
            }
        }
        *(uint4*)(sAh + arow * 40 + apart)     = *(uint4*)hh;
        *(uint4*)(sAh + arow * 40 + apart + 8) = *(uint4*)(hh + 8);
        *(uint4*)(sAl + arow * 40 + apart)     = *(uint4*)ll;
        *(uint4*)(sAl + arow * 40 + apart + 8) = *(uint4*)(ll + 8);
        *(uint4*)(sBh + bkr * 72 + bnp) = rbh;
        *(uint4*)(sBl + bkr * 72 + bnp) = rbl;
        __syncthreads();

        const bool more = (kc + KC) < 128;
        if (more) {
            const float* ap = z + (size_t)(brow + arow) * 128 + kc + KC + apart;
#pragma unroll
            for (int j = 0; j < 4; j++) ra[j] = *(const float4*)(ap + j * 4);
            rbh = *(const uint4*)(g_zwh + (kc + KC + bkr) * 64 + bnp);
            rbl = *(const uint4*)(g_zwl + (kc + KC + bkr) * 64 + bnp);
        }

#pragma unroll
        for (int ks = 0; ks < 2; ks++) {
            const int kk = ks * 16;
            unsigned afh[4][4], afl[4][4];
            const int g = lane >> 3, r = lane & 7;
#pragma unroll
            for (int mi = 0; mi < 4; mi++) {
                const int row = wm * 64 + mi * 16 + (g & 1) * 8 + r;
                const int col = kk + (g >> 1) * 8;
                ldsm_x4(afh[mi], sAh_u + (unsigned)(row * 40 + col) * 2u);
                ldsm_x4(afl[mi], sAl_u + (unsigned)(row * 40 + col) * 2u);
            }
            unsigned bfh[2][2], bfl[2][2];
            const int g2 = (lane >> 3) & 1, r2 = lane & 7;
#pragma unroll
            for (int ni = 0; ni < 2; ni++) {
                const int krow = kk + g2 * 8 + r2;
                const int col  = wn * 16 + ni * 8;
                ldsm_x2t(bfh[ni], sBh_u + (unsigned)(krow * 72 + col) * 2u);
                ldsm_x2t(bfl[ni], sBl_u + (unsigned)(krow * 72 + col) * 2u);
            }
#pragma unroll
            for (int mi = 0; mi < 4; mi++)
#pragma unroll
                for (int ni = 0; ni < 2; ni++) {
                    mma_bf16(acc[mi][ni], afh[mi], bfh[ni]);
                    mma_bf16(acc[mi][ni], afh[mi], bfl[ni]);
                    mma_bf16(acc[mi][ni], afl[mi], bfh[ni]);
                }
        }
        if (more) __syncthreads();
    }

    const float S = 0.5773502691896258f;
    const int gr = lane >> 2, gc = (lane & 3) * 2;
#pragma unroll
    for (int mi = 0; mi < 4; mi++) {
        const long e0 = brow + wm * 64 + mi * 16 + gr;
#pragma unroll
        for (int ni = 0; ni < 2; ni++) {
            const int colb = wn * 16 + ni * 8 + gc;
#pragma unroll
            for (int r = 0; r < 4; r++) {
                const long e   = e0 + (r >> 1) * 8;
                const int  col = colb + (r & 1);
                const float v = acc[mi][ni][r];
                if (col < 12)   // transposed: [n][h][k], n=e>>5, k=e&31
                    g_bpairT[(e >> 5) * 384 + col * 32 + (e & 31)] = S * (v + __ldg(bb + col));
                else if (col < 44)
                    g_pairz[e * 32 + (col - 12)] = v + __ldg(bdz + (col - 12));
            }
        }
    }
}

// ---------------- fused attention: staged coalesced logits (no shfl tree) ----------------
__device__ __forceinline__ void put_cat(size_t n, int idx, float v)
{
    split_store(g_cath + n * 960 + idx, g_catl + n * 960 + idx, v);
}

__global__ __launch_bounds__(384) void attn_kernel(const int* __restrict__ edge_index,
                                                   const float* __restrict__ rot,
                                                   const float* __restrict__ trans,
                                                   const float* __restrict__ mask,
                                                   const float* __restrict__ head_weights)
{
    int n = blockIdx.x;
    int t = threadIdx.x;
    __shared__ int   s_idx[32];
    __shared__ float s_mask[32];
    __shared__ float s_q[192];
    __shared__ float s_qp[144];
    __shared__ float s_R[9], s_T[3];
    __shared__ float s_hw[12];
    __shared__ float s_a[12][33];
    __shared__ float s_opt[288];
    __shared__ float s_stage[12 * 32 * 29];   // per-head [32 neighbors][29], stride 29 conflict-free

    if (t < 32) {
        int nb = edge_index[n * 32 + t];
        s_idx[t]  = nb;
        s_mask[t] = mask[nb];
    }
    if (t >= 32 && t < 224)  s_q [t - 32]  = g_proj[(size_t)n * 1152 + (t - 32)];
    if (t >= 224 && t < 368) s_qp[t - 224] = g_qpts[(size_t)n * 144 + (t - 224)];
    if (t >= 368 && t < 377) s_R [t - 368] = rot  [n * 9 + (t - 368)];
    if (t >= 377 && t < 380) s_T [t - 377] = trans[n * 3 + (t - 377)];
    if (t < 12) {
        float x = head_weights[t];
        float sp = (x > 20.f) ? x : log1pf(expf(x));
        s_hw[t] = sp * 0.13608276348795434f;   // softplus * sqrt(1/54)
    }
    __syncthreads();

    // logits: warp h. Phase A: coalesced cooperative stage of 32 neighbor lines.
    // Phase B: lane k computes its own logit from smem (no shfl, conflict-free).
    {
        const int h = t >> 5, lane = t & 31;
        float* stg = s_stage + h * 32 * 29;
#pragma unroll 4
        for (int k = 0; k < 32; k++) {
            int nb = s_idx[k];
            if (lane < 28)
                stg[k * 29 + lane] = g_attn[((size_t)nb * 12 + h) * 32 + lane];
        }
        __syncwarp();

        const float* row = stg + lane * 29;
        float dot = 0.f;
#pragma unroll
        for (int c = 0; c < 16; c++) dot = fmaf(s_q[h * 16 + c], row[c], dot);
        float pt = 0.f;
#pragma unroll
        for (int j = 0; j < 12; j++) {
            float d = s_qp[h * 12 + j] - row[16 + j];
            pt = fmaf(d, d, pt);
        }
        float logit = dot * 0.14433756729740643f
                    + g_bpairT[(size_t)n * 384 + h * 32 + lane]
                    - 0.5f * s_hw[h] * pt
                    + 100000.0f * (s_mask[lane] - 1.0f);
        float m = logit;
#pragma unroll
        for (int o = 16; o; o >>= 1) m = fmaxf(m, __shfl_xor_sync(0xffffffffu, m, o));
        float e = expf(logit - m);
        float ssum = e;
#pragma unroll
        for (int o = 16; o; o >>= 1) ssum += __shfl_xor_sync(0xffffffffu, ssum, o);
        s_a[h][lane] = e / ssum;
    }
    __syncthreads();

    // o: scalar part, 192 outputs (coalesced across lanes)
    if (t < 192) {
        int h = t >> 4, c = t & 15;
        float acc = 0.f;
#pragma unroll 4
        for (int k = 0; k < 32; k++)
            acc = fmaf(s_a[h][k], g_proj[(size_t)s_idx[k] * 1152 + 192 + h * 32 + 16 + c], acc);
        put_cat(n, h * 16 + c, acc);
    }
    // o_pt: 288 outputs
    if (t < 288) {
        int j = t / 3, i = t - j * 3;
        int h = j >> 3, p = j & 7;
        float acc = 0.f;
#pragma unroll 4
        for (int k = 0; k < 32; k++)
            acc = fmaf(s_a[h][k], g_kvpts[(size_t)s_idx[k] * 432 + h * 36 + (4 + p) * 3 + i], acc);
        s_opt[t] = acc;
    }
    // o_pair: direct coalesced reads (12 warps share each line -> L1 hits)
    {
        int h = t >> 5, c = t & 31;
        float acc = 0.f;
#pragma unroll 4
        for (int k = 0; k < 32; k++)
            acc = fmaf(s_a[h][k], g_pairz[((size_t)n * 32 + k) * 32 + c], acc);
        put_cat(n, 576 + h * 32 + c, acc);
    }
    __syncthreads();
    if (t < 96) {
        float gx = s_opt[t * 3 + 0] - s_T[0];
        float gy = s_opt[t * 3 + 1] - s_T[1];
        float gz = s_opt[t * 3 + 2] - s_T[2];
        float lx = fmaf(s_R[0], gx, fmaf(s_R[3], gy, s_R[6] * gz));
        float ly = fmaf(s_R[1], gx, fmaf(s_R[4], gy, s_R[7] * gz));
        float lz = fmaf(s_R[2], gx, fmaf(s_R[5], gy, s_R[8] * gz));
        put_cat(n, 192 + t, lx);
        put_cat(n, 288 + t, ly);
        put_cat(n, 384 + t, lz);
        put_cat(n, 480 + t, sqrtf(fmaf(lx, lx, fmaf(ly, ly, fmaf(lz, lz, 1e-8f)))));
    }
}

// ---------------- launch: prep(1) gemm_proj(2) transform(3) zproj(4=profiled) attn(5) gemm_out(6) ----------------
extern "C" void kernel_launch(void* const* d_in, const int* in_sizes, int n_in,
                              void* d_out, int out_size)
{
    const float* s     = (const float*)d_in[0];
    const float* z     = (const float*)d_in[1];
    const int*   ei    = (const int*)  d_in[2];
    const float* rot   = (const float*)d_in[3];
    const float* trans = (const float*)d_in[4];
    const float* mask  = (const float*)d_in[5];
    const float* w_q   = (const float*)d_in[6];
    const float* b_q   = (const float*)d_in[7];
    const float* w_kv  = (const float*)d_in[8];
    const float* b_kv  = (const float*)d_in[9];
    const float* w_qp  = (const float*)d_in[10];
    const float* b_qp  = (const float*)d_in[11];
    const float* w_kvp = (const float*)d_in[12];
    const float* b_kvp = (const float*)d_in[13];
    const float* w_b   = (const float*)d_in[14];
    const float* b_b   = (const float*)d_in[15];
    const float* w_dz  = (const float*)d_in[16];
    const float* b_dz  = (const float*)d_in[17];
    const float* hw    = (const float*)d_in[18];
    const float* w_out = (const float*)d_in[19];
    const float* b_out = (const float*)d_in[20];
    float* out = (float*)d_out;

    prep_all<<<512, 256>>>((const float4*)s, w_q, w_kv, w_qp, w_kvp,
                           b_q, b_kv, b_qp, b_kvp, w_out, w_b, w_dz);        // slot 1
    gemm_proj_mma<<<dim3(1152 / BN, NNODES / BM), 256>>>();                  // slot 2
    transform_pack<<<NNODES, 256>>>(rot, trans);                             // slot 3
    zproj_mma<<<(NNODES * KNBR) / BM, 256>>>(z, b_b, b_dz);                  // slot 4 (profiled)
    attn_kernel<<<NNODES, 384>>>(ei, rot, trans, mask, hw);                  // slot 5
    gemm_out_mma<<<dim3(384 / BN, NNODES / BM), 256>>>(b_out, out);          // slot 6
}

// round 14
// speedup vs baseline: 1.1265x; 1.1182x over previous
#include <cuda_runtime.h>
#include <cuda_bf16.h>
#include <math.h>

#define NNODES 8192
#define KNBR   32

// ---------------- scratch (static device arrays; no allocation) ----------------
__device__ __align__(16) float g_proj  [NNODES * 1152];   // q(192)|kv(384)|qp(144)|kvp(432)
__device__ __align__(16) float g_bcat  [1152];
__device__ __align__(16) float g_qpts  [NNODES * 144];
__device__ __align__(16) float g_kvpts [NNODES * 432];
__device__ __align__(16) float g_bpairT[NNODES * 384];        // [n][h][k] transposed, coalesced
__device__ __align__(16) float g_pairz [NNODES * KNBR * 32];
__device__ __align__(16) __nv_bfloat16 g_sh   [NNODES * 384];
__device__ __align__(16) __nv_bfloat16 g_sl   [NNODES * 384];
__device__ __align__(16) __nv_bfloat16 g_wcath[384 * 1152];
__device__ __align__(16) __nv_bfloat16 g_wcatl[384 * 1152];
__device__ __align__(16) __nv_bfloat16 g_wouth[960 * 384];
__device__ __align__(16) __nv_bfloat16 g_woutl[960 * 384];
__device__ __align__(16) __nv_bfloat16 g_cath [NNODES * 960];
__device__ __align__(16) __nv_bfloat16 g_catl [NNODES * 960];
__device__ __align__(16) __nv_bfloat16 g_zwh  [128 * 64];
__device__ __align__(16) __nv_bfloat16 g_zwl  [128 * 64];

// ---------------- helpers ----------------
__device__ __forceinline__ void split_store(__nv_bfloat16* ph, __nv_bfloat16* pl, float x)
{
    __nv_bfloat16 h = __float2bfloat16(x);
    *ph = h;
    *pl = __float2bfloat16(x - __bfloat162float(h));
}

__device__ __forceinline__ void mma_bf16(float* c, const unsigned* a, const unsigned* b)
{
    asm volatile(
        "mma.sync.aligned.m16n8k16.row.col.f32.bf16.bf16.f32 "
        "{%0,%1,%2,%3}, {%4,%5,%6,%7}, {%8,%9}, {%0,%1,%2,%3};"
        : "+f"(c[0]), "+f"(c[1]), "+f"(c[2]), "+f"(c[3])
        : "r"(a[0]), "r"(a[1]), "r"(a[2]), "r"(a[3]), "r"(b[0]), "r"(b[1]));
}
__device__ __forceinline__ void ldsm_x4(unsigned* d, unsigned addr)
{
    asm volatile("ldmatrix.sync.aligned.m8n8.x4.shared.b16 {%0,%1,%2,%3}, [%4];"
                 : "=r"(d[0]), "=r"(d[1]), "=r"(d[2]), "=r"(d[3]) : "r"(addr));
}
__device__ __forceinline__ void ldsm_x2t(unsigned* d, unsigned addr)
{
    asm volatile("ldmatrix.sync.aligned.m8n8.x2.trans.shared.b16 {%0,%1}, [%2];"
                 : "=r"(d[0]), "=r"(d[1]) : "r"(addr));
}

// ---------------- prep_all ----------------
__global__ void prep_all(const float4* __restrict__ s,
                         const float* __restrict__ wq, const float* __restrict__ wkv,
                         const float* __restrict__ wqp, const float* __restrict__ wkvp,
                         const float* __restrict__ bq, const float* __restrict__ bkv,
                         const float* __restrict__ bqp, const float* __restrict__ bkvp,
                         const float* __restrict__ wout,
                         const float* __restrict__ wb, const float* __restrict__ wdz)
{
    const int t  = blockIdx.x * blockDim.x + threadIdx.x;
    const int st = gridDim.x * blockDim.x;
    for (int i = t; i < NNODES * 384 / 4; i += st) {
        float4 v = s[i];
        __nv_bfloat16* ph = g_sh + i * 4;
        __nv_bfloat16* pl = g_sl + i * 4;
        split_store(ph + 0, pl + 0, v.x);
        split_store(ph + 1, pl + 1, v.y);
        split_store(ph + 2, pl + 2, v.z);
        split_store(ph + 3, pl + 3, v.w);
    }
    for (int i = t; i < 384 * 1152; i += st) {
        int r = i / 1152, c = i % 1152;
        float v;
        if      (c < 192) v = wq  [r * 192 + c];
        else if (c < 576) v = wkv [r * 384 + (c - 192)];
        else if (c < 720) v = wqp [r * 144 + (c - 576)];
        else              v = wkvp[r * 432 + (c - 720)];
        split_store(g_wcath + i, g_wcatl + i, v);
    }
    for (int i = t; i < 960 * 384; i += st)
        split_store(g_wouth + i, g_woutl + i, wout[i]);
    for (int i = t; i < 128 * 64; i += st) {
        int r = i >> 6, c = i & 63;
        float v = 0.f;
        if      (c < 12) v = wb [r * 12 + c];
        else if (c < 44) v = wdz[r * 32 + (c - 12)];
        split_store(g_zwh + i, g_zwl + i, v);
    }
    for (int i = t; i < 1152; i += st) {
        float v;
        if      (i < 192) v = bq [i];
        else if (i < 576) v = bkv[i - 192];
        else if (i < 720) v = bqp[i - 576];
        else              v = bkvp[i - 720];
        g_bcat[i] = v;
    }
}

// ---------------- bf16 hi/lo compensated tensor-core GEMM body ----------------
#define BM 128
#define BN 64
#define KC 32
template<int K>
__device__ __forceinline__ void mma_gemm_body(
    int bx, int by,
    const __nv_bfloat16* __restrict__ Ah, const __nv_bfloat16* __restrict__ Al,
    const __nv_bfloat16* __restrict__ Bh, const __nv_bfloat16* __restrict__ Bl,
    const float* __restrict__ bias, float* __restrict__ C, const int N,
    __nv_bfloat16* sAh, __nv_bfloat16* sAl, __nv_bfloat16* sBh, __nv_bfloat16* sBl)
{
    const int tid  = threadIdx.x;
    const int lane = tid & 31, warp = tid >> 5;
    const int wm = warp >> 2, wn = warp & 3;
    const long brow = (long)by * BM;
    const long bcol = (long)bx * BN;

    float acc[4][2][4];
#pragma unroll
    for (int mi = 0; mi < 4; mi++)
#pragma unroll
        for (int ni = 0; ni < 2; ni++)
#pragma unroll
            for (int r = 0; r < 4; r++) acc[mi][ni][r] = 0.f;

    const int arow  = tid >> 1, apart = (tid & 1) * 16;
    const int bkr   = tid >> 3, bnp   = (tid & 7) * 8;

    const unsigned sAh_u = (unsigned)__cvta_generic_to_shared(sAh);
    const unsigned sAl_u = (unsigned)__cvta_generic_to_shared(sAl);
    const unsigned sBh_u = (unsigned)__cvta_generic_to_shared(sBh);
    const unsigned sBl_u = (unsigned)__cvta_generic_to_shared(sBl);

    uint4 rah0, rah1, ral0, ral1, rbh, rbl;
    {
        const size_t aoff = (size_t)(brow + arow) * K + apart;
        rah0 = *(const uint4*)(Ah + aoff); rah1 = *(const uint4*)(Ah + aoff + 8);
        ral0 = *(const uint4*)(Al + aoff); ral1 = *(const uint4*)(Al + aoff + 8);
        const size_t boff = (size_t)bkr * N + bcol + bnp;
        rbh = *(const uint4*)(Bh + boff);
        rbl = *(const uint4*)(Bl + boff);
    }

    for (int kc = 0; kc < K; kc += KC) {
        *(uint4*)(sAh + arow * 40 + apart)     = rah0;
        *(uint4*)(sAh + arow * 40 + apart + 8) = rah1;
        *(uint4*)(sAl + arow * 40 + apart)     = ral0;
        *(uint4*)(sAl + arow * 40 + apart + 8) = ral1;
        *(uint4*)(sBh + bkr * 72 + bnp) = rbh;
        *(uint4*)(sBl + bkr * 72 + bnp) = rbl;
        __syncthreads();

        const bool more = (kc + KC) < K;
        if (more) {
            const size_t aoff = (size_t)(brow + arow) * K + kc + KC + apart;
            rah0 = *(const uint4*)(Ah + aoff); rah1 = *(const uint4*)(Ah + aoff + 8);
            ral0 = *(const uint4*)(Al + aoff); ral1 = *(const uint4*)(Al + aoff + 8);
            const size_t boff = (size_t)(kc + KC + bkr) * N + bcol + bnp;
            rbh = *(const uint4*)(Bh + boff);
            rbl = *(const uint4*)(Bl + boff);
        }

#pragma unroll
        for (int ks = 0; ks < 2; ks++) {
            const int kk = ks * 16;
            unsigned afh[4][4], afl[4][4];
            const int g = lane >> 3, r = lane & 7;
#pragma unroll
            for (int mi = 0; mi < 4; mi++) {
                const int row = wm * 64 + mi * 16 + (g & 1) * 8 + r;
                const int col = kk + (g >> 1) * 8;
                ldsm_x4(afh[mi], sAh_u + (unsigned)(row * 40 + col) * 2u);
                ldsm_x4(afl[mi], sAl_u + (unsigned)(row * 40 + col) * 2u);
            }
            unsigned bfh[2][2], bfl[2][2];
            const int g2 = (lane >> 3) & 1, r2 = lane & 7;
#pragma unroll
            for (int ni = 0; ni < 2; ni++) {
                const int krow = kk + g2 * 8 + r2;
                const int col  = wn * 16 + ni * 8;
                ldsm_x2t(bfh[ni], sBh_u + (unsigned)(krow * 72 + col) * 2u);
                ldsm_x2t(bfl[ni], sBl_u + (unsigned)(krow * 72 + col) * 2u);
            }
#pragma unroll
            for (int mi = 0; mi < 4; mi++)
#pragma unroll
                for (int ni = 0; ni < 2; ni++) {
                    mma_bf16(acc[mi][ni], afh[mi], bfh[ni]);
                    mma_bf16(acc[mi][ni], afh[mi], bfl[ni]);
                    mma_bf16(acc[mi][ni], afl[mi], bfh[ni]);
                }
        }
        if (more) __syncthreads();
    }

    const int gr = lane >> 2, gc = (lane & 3) * 2;
#pragma unroll
    for (int mi = 0; mi < 4; mi++) {
        const long row0 = brow + wm * 64 + mi * 16 + gr;
#pragma unroll
        for (int ni = 0; ni < 2; ni++) {
            const long col0 = bcol + wn * 16 + ni * 8 + gc;
            const float b0 = bias[col0], b1 = bias[col0 + 1];
            float2 v0 = make_float2(acc[mi][ni][0] + b0, acc[mi][ni][1] + b1);
            float2 v1 = make_float2(acc[mi][ni][2] + b0, acc[mi][ni][3] + b1);
            *(float2*)&C[row0 * N + col0]       = v0;
            *(float2*)&C[(row0 + 8) * N + col0] = v1;
        }
    }
}

// ---------------- zproj role body (fused fp32->bf16 conversion) ----------------
__device__ __forceinline__ void zproj_body(
    int blk, const float* __restrict__ z,
    const float* __restrict__ bb, const float* __restrict__ bdz,
    __nv_bfloat16* sAh, __nv_bfloat16* sAl, __nv_bfloat16* sBh, __nv_bfloat16* sBl)
{
    const int tid  = threadIdx.x;
    const int lane = tid & 31, warp = tid >> 5;
    const int wm = warp >> 2, wn = warp & 3;
    const long brow = (long)blk * BM;

    float acc[4][2][4];
#pragma unroll
    for (int mi = 0; mi < 4; mi++)
#pragma unroll
        for (int ni = 0; ni < 2; ni++)
#pragma unroll
            for (int r = 0; r < 4; r++) acc[mi][ni][r] = 0.f;

    const int arow  = tid >> 1, apart = (tid & 1) * 16;
    const int bkr   = tid >> 3, bnp   = (tid & 7) * 8;

    const unsigned sAh_u = (unsigned)__cvta_generic_to_shared(sAh);
    const unsigned sAl_u = (unsigned)__cvta_generic_to_shared(sAl);
    const unsigned sBh_u = (unsigned)__cvta_generic_to_shared(sBh);
    const unsigned sBl_u = (unsigned)__cvta_generic_to_shared(sBl);

    float4 ra[4];
    uint4 rbh, rbl;
    {
        const float* ap = z + (size_t)(brow + arow) * 128 + apart;
#pragma unroll
        for (int j = 0; j < 4; j++) ra[j] = *(const float4*)(ap + j * 4);
        rbh = *(const uint4*)(g_zwh + bkr * 64 + bnp);
        rbl = *(const uint4*)(g_zwl + bkr * 64 + bnp);
    }

    for (int kc = 0; kc < 128; kc += KC) {
        __nv_bfloat16 hh[16], ll[16];
#pragma unroll
        for (int j = 0; j < 4; j++) {
            float v[4] = {ra[j].x, ra[j].y, ra[j].z, ra[j].w};
#pragma unroll
            for (int q = 0; q < 4; q++) {
                __nv_bfloat16 h = __float2bfloat16(v[q]);
                hh[j * 4 + q] = h;
                ll[j * 4 + q] = __float2bfloat16(v[q] - __bfloat162float(h));
            }
        }
        *(uint4*)(sAh + arow * 40 + apart)     = *(uint4*)hh;
        *(uint4*)(sAh + arow * 40 + apart + 8) = *(uint4*)(hh + 8);
        *(uint4*)(sAl + arow * 40 + apart)     = *(uint4*)ll;
        *(uint4*)(sAl + arow * 40 + apart + 8) = *(uint4*)(ll + 8);
        *(uint4*)(sBh + bkr * 72 + bnp) = rbh;
        *(uint4*)(sBl + bkr * 72 + bnp) = rbl;
        __syncthreads();

        const bool more = (kc + KC) < 128;
        if (more) {
            const float* ap = z + (size_t)(brow + arow) * 128 + kc + KC + apart;
#pragma unroll
            for (int j = 0; j < 4; j++) ra[j] = *(const float4*)(ap + j * 4);
            rbh = *(const uint4*)(g_zwh + (kc + KC + bkr) * 64 + bnp);
            rbl = *(const uint4*)(g_zwl + (kc + KC + bkr) * 64 + bnp);
        }

#pragma unroll
        for (int ks = 0; ks < 2; ks++) {
            const int kk = ks * 16;
            unsigned afh[4][4], afl[4][4];
            const int g = lane >> 3, r = lane & 7;
#pragma unroll
            for (int mi = 0; mi < 4; mi++) {
                const int row = wm * 64 + mi * 16 + (g & 1) * 8 + r;
                const int col = kk + (g >> 1) * 8;
                ldsm_x4(afh[mi], sAh_u + (unsigned)(row * 40 + col) * 2u);
                ldsm_x4(afl[mi], sAl_u + (unsigned)(row * 40 + col) * 2u);
            }
            unsigned bfh[2][2], bfl[2][2];
            const int g2 = (lane >> 3) & 1, r2 = lane & 7;
#pragma unroll
            for (int ni = 0; ni < 2; ni++) {
                const int krow = kk + g2 * 8 + r2;
                const int col  = wn * 16 + ni * 8;
                ldsm_x2t(bfh[ni], sBh_u + (unsigned)(krow * 72 + col) * 2u);
                ldsm_x2t(bfl[ni], sBl_u + (unsigned)(krow * 72 + col) * 2u);
            }
#pragma unroll
            for (int mi = 0; mi < 4; mi++)
#pragma unroll
                for (int ni = 0; ni < 2; ni++) {
                    mma_bf16(acc[mi][ni], afh[mi], bfh[ni]);
                    mma_bf16(acc[mi][ni], afh[mi], bfl[ni]);
                    mma_bf16(acc[mi][ni], afl[mi], bfh[ni]);
                }
        }
        if (more) __syncthreads();
    }

    const float S = 0.5773502691896258f;
    const int gr = lane >> 2, gc = (lane & 3) * 2;
#pragma unroll
    for (int mi = 0; mi < 4; mi++) {
        const long e0 = brow + wm * 64 + mi * 16 + gr;
#pragma unroll
        for (int ni = 0; ni < 2; ni++) {
            const int colb = wn * 16 + ni * 8 + gc;
#pragma unroll
            for (int r = 0; r < 4; r++) {
                const long e   = e0 + (r >> 1) * 8;
                const int  col = colb + (r & 1);
                const float v = acc[mi][ni][r];
                if (col < 12)
                    g_bpairT[(e >> 5) * 384 + col * 32 + (e & 31)] = S * (v + __ldg(bb + col));
                else if (col < 44)
                    g_pairz[e * 32 + (col - 12)] = v + __ldg(bdz + (col - 12));
            }
        }
    }
}

// ---------------- fused heavy kernel: gemm_proj (blocks 0..1151) + zproj (1152..3199) ----------------
#define GP_BLOCKS (18 * 64)                 // (1152/BN) x (NNODES/BM)
#define ZP_BLOCKS ((NNODES * KNBR) / BM)    // 2048
__global__ __launch_bounds__(256) void gz_fused(const float* __restrict__ z,
                                                const float* __restrict__ bb,
                                                const float* __restrict__ bdz)
{
    __shared__ __nv_bfloat16 sAh[BM * 40], sAl[BM * 40];
    __shared__ __nv_bfloat16 sBh[KC * 72], sBl[KC * 72];
    const int b = blockIdx.x;
    if (b < GP_BLOCKS) {
        mma_gemm_body<384>(b % 18, b / 18, g_sh, g_sl, g_wcath, g_wcatl,
                           g_bcat, g_proj, 1152, sAh, sAl, sBh, sBl);
    } else {
        zproj_body(b - GP_BLOCKS, z, bb, bdz, sAh, sAl, sBh, sBl);
    }
}

__global__ __launch_bounds__(256) void gemm_out_mma(const float* __restrict__ bout,
                                                    float* __restrict__ out)
{
    __shared__ __nv_bfloat16 sAh[BM * 40], sAl[BM * 40];
    __shared__ __nv_bfloat16 sBh[KC * 72], sBl[KC * 72];
    mma_gemm_body<960>(blockIdx.x, blockIdx.y, g_cath, g_catl, g_wouth, g_woutl,
                       bout, out, 384, sAh, sAl, sBh, sBl);
}

// ---------------- rigid transform of qp/kvp points (simple, high-occ) ----------------
__global__ __launch_bounds__(192) void transform_points(const float* __restrict__ rot,
                                                        const float* __restrict__ trans)
{
    int n = blockIdx.x;
    __shared__ float R[9], T[3];
    int t = threadIdx.x;
    if (t < 9) R[t] = rot[n * 9 + t];
    if (t < 3) T[t] = trans[n * 3 + t];
    __syncthreads();
    if (t < 48) {
        const float* base = g_proj + (size_t)n * 1152 + 576;
        float x = base[t], y = base[48 + t], zz = base[96 + t];
        float* o = g_qpts + (size_t)n * 144 + t * 3;
        o[0] = fmaf(R[0], x, fmaf(R[1], y, fmaf(R[2], zz, T[0])));
        o[1] = fmaf(R[3], x, fmaf(R[4], y, fmaf(R[5], zz, T[1])));
        o[2] = fmaf(R[6], x, fmaf(R[7], y, fmaf(R[8], zz, T[2])));
    } else {
        int j = t - 48;
        const float* base = g_proj + (size_t)n * 1152 + 720;
        float x = base[j], y = base[144 + j], zz = base[288 + j];
        float* o = g_kvpts + (size_t)n * 432 + j * 3;
        o[0] = fmaf(R[0], x, fmaf(R[1], y, fmaf(R[2], zz, T[0])));
        o[1] = fmaf(R[3], x, fmaf(R[4], y, fmaf(R[5], zz, T[1])));
        o[2] = fmaf(R[6], x, fmaf(R[7], y, fmaf(R[8], zz, T[2])));
    }
}

// ---------------- fused attention (r8-style; bpairT coalesced logit bias) ----------------
__device__ __forceinline__ void put_cat(size_t n, int idx, float v)
{
    split_store(g_cath + n * 960 + idx, g_catl + n * 960 + idx, v);
}

__global__ __launch_bounds__(384) void attn_kernel(const int* __restrict__ edge_index,
                                                   const float* __restrict__ rot,
                                                   const float* __restrict__ trans,
                                                   const float* __restrict__ mask,
                                                   const float* __restrict__ head_weights)
{
    int n = blockIdx.x;
    int t = threadIdx.x;
    __shared__ int   s_idx[32];
    __shared__ float s_mask[32];
    __shared__ float s_q[192];
    __shared__ float s_qp[144];
    __shared__ float s_R[9], s_T[3];
    __shared__ float s_hw[12];
    __shared__ float s_a[12][33];
    __shared__ float s_opt[288];
    __shared__ float s_pz[32][33];

    if (t < 32) {
        int nb = edge_index[n * 32 + t];
        s_idx[t]  = nb;
        s_mask[t] = mask[nb];
    }
    if (t >= 32 && t < 224)  s_q [t - 32]  = g_proj[(size_t)n * 1152 + (t - 32)];
    if (t >= 224 && t < 368) s_qp[t - 224] = g_qpts[(size_t)n * 144 + (t - 224)];
    if (t >= 368 && t < 377) s_R [t - 368] = rot  [n * 9 + (t - 368)];
    if (t >= 377 && t < 380) s_T [t - 377] = trans[n * 3 + (t - 377)];
    if (t < 12) {
        float x = head_weights[t];
        float sp = (x > 20.f) ? x : log1pf(expf(x));
        s_hw[t] = sp * 0.13608276348795434f;   // softplus * sqrt(1/54)
    }
    __syncthreads();

    // logits + softmax: warp h, lane k (divergent scalar gather; best measured form)
    {
        int h = t >> 5, k = t & 31;
        int nb = s_idx[k];
        const float* kg = g_proj + (size_t)nb * 1152 + 192 + h * 32;
        float dot = 0.f;
#pragma unroll
        for (int c = 0; c < 16; c++) dot = fmaf(s_q[h * 16 + c], kg[c], dot);
        const float* kp = g_kvpts + (size_t)nb * 432 + h * 36;
        float pt = 0.f;
#pragma unroll
        for (int pi = 0; pi < 12; pi++) {
            float d = s_qp[h * 12 + pi] - kp[pi];
            pt = fmaf(d, d, pt);
        }
        float logit = dot * 0.14433756729740643f
                    + g_bpairT[(size_t)n * 384 + h * 32 + k]   // coalesced across lanes
                    - 0.5f * s_hw[h] * pt
                    + 100000.0f * (s_mask[k] - 1.0f);
        float m = logit;
#pragma unroll
        for (int o = 16; o; o >>= 1) m = fmaxf(m, __shfl_xor_sync(0xffffffffu, m, o));
        float e = expf(logit - m);
        float ssum = e;
#pragma unroll
        for (int o = 16; o; o >>= 1) ssum += __shfl_xor_sync(0xffffffffu, ssum, o);
        s_a[h][k] = e / ssum;
    }
    for (int i = t; i < 32 * 32; i += 384)
        s_pz[i >> 5][i & 31] = g_pairz[((size_t)n * 32 + (i >> 5)) * 32 + (i & 31)];
    __syncthreads();

    // o: scalar part, 192 outputs (coalesced across lanes)
    if (t < 192) {
        int h = t >> 4, c = t & 15;
        float acc = 0.f;
#pragma unroll 4
        for (int k = 0; k < 32; k++)
            acc = fmaf(s_a[h][k], g_proj[(size_t)s_idx[k] * 1152 + 192 + h * 32 + 16 + c], acc);
        put_cat(n, h * 16 + c, acc);
    }
    // o_pt: 288 outputs
    if (t < 288) {
        int j = t / 3, i = t - j * 3;
        int h = j >> 3, p = j & 7;
        float acc = 0.f;
#pragma unroll 4
        for (int k = 0; k < 32; k++)
            acc = fmaf(s_a[h][k], g_kvpts[(size_t)s_idx[k] * 432 + h * 36 + (4 + p) * 3 + i], acc);
        s_opt[t] = acc;
    }
    // o_pair: smem-resident
    {
        int h = t >> 5, c = t & 31;
        float acc = 0.f;
#pragma unroll
        for (int k = 0; k < 32; k++)
            acc = fmaf(s_a[h][k], s_pz[k][c], acc);
        put_cat(n, 576 + h * 32 + c, acc);
    }
    __syncthreads();
    if (t < 96) {
        float gx = s_opt[t * 3 + 0] - s_T[0];
        float gy = s_opt[t * 3 + 1] - s_T[1];
        float gz = s_opt[t * 3 + 2] - s_T[2];
        float lx = fmaf(s_R[0], gx, fmaf(s_R[3], gy, s_R[6] * gz));
        float ly = fmaf(s_R[1], gx, fmaf(s_R[4], gy, s_R[7] * gz));
        float lz = fmaf(s_R[2], gx, fmaf(s_R[5], gy, s_R[8] * gz));
        put_cat(n, 192 + t, lx);
        put_cat(n, 288 + t, ly);
        put_cat(n, 384 + t, lz);
        put_cat(n, 480 + t, sqrtf(fmaf(lx, lx, fmaf(ly, ly, fmaf(lz, lz, 1e-8f)))));
    }
}

// ---------------- launch: prep(1) gz_fused(2) transform(3) attn(4=profiled) gemm_out(5) ----------------
extern "C" void kernel_launch(void* const* d_in, const int* in_sizes, int n_in,
                              void* d_out, int out_size)
{
    const float* s     = (const float*)d_in[0];
    const float* z     = (const float*)d_in[1];
    const int*   ei    = (const int*)  d_in[2];
    const float* rot   = (const float*)d_in[3];
    const float* trans = (const float*)d_in[4];
    const float* mask  = (const float*)d_in[5];
    const float* w_q   = (const float*)d_in[6];
    const float* b_q   = (const float*)d_in[7];
    const float* w_kv  = (const float*)d_in[8];
    const float* b_kv  = (const float*)d_in[9];
    const float* w_qp  = (const float*)d_in[10];
    const float* b_qp  = (const float*)d_in[11];
    const float* w_kvp = (const float*)d_in[12];
    const float* b_kvp = (const float*)d_in[13];
    const float* w_b   = (const float*)d_in[14];
    const float* b_b   = (const float*)d_in[15];
    const float* w_dz  = (const float*)d_in[16];
    const float* b_dz  = (const float*)d_in[17];
    const float* hw    = (const float*)d_in[18];
    const float* w_out = (const float*)d_in[19];
    const float* b_out = (const float*)d_in[20];
    float* out = (float*)d_out;

    prep_all<<<512, 256>>>((const float4*)s, w_q, w_kv, w_qp, w_kvp,
                           b_q, b_kv, b_qp, b_kvp, w_out, w_b, w_dz);        // slot 1
    gz_fused<<<GP_BLOCKS + ZP_BLOCKS, 256>>>(z, b_b, b_dz);                  // slot 2 (overlapped heavies)
    transform_points<<<NNODES, 192>>>(rot, trans);                           // slot 3
    attn_kernel<<<NNODES, 384>>>(ei, rot, trans, mask, hw);                  // slot 4 (profiled)
    gemm_out_mma<<<dim3(384 / BN, NNODES / BM), 256>>>(b_out, out);          // slot 5
}

// round 15
// speedup vs baseline: 1.1726x; 1.0409x over previous
#include <cuda_runtime.h>
#include <cuda_bf16.h>
#include <math.h>

#define NNODES 8192
#define KNBR   32

// ---------------- scratch (static device arrays; no allocation) ----------------
__device__ __align__(16) float g_proj  [NNODES * 1152];   // q(192)|kv(384)|qp(144)|kvp(432)
__device__ __align__(16) float g_bcat  [1152];
__device__ __align__(16) float g_qpts  [NNODES * 144];
__device__ __align__(16) float g_kvpts [NNODES * 432];
__device__ __align__(16) float g_bpairT[NNODES * 384];
__device__ __align__(16) float g_pairz [NNODES * KNBR * 32];
__device__ __align__(16) __nv_bfloat16 g_sh   [NNODES * 384];
__device__ __align__(16) __nv_bfloat16 g_sl   [NNODES * 384];
__device__ __align__(16) __nv_bfloat16 g_wcath[384 * 1152];
__device__ __align__(16) __nv_bfloat16 g_wcatl[384 * 1152];
__device__ __align__(16) __nv_bfloat16 g_wouth[960 * 384];
__device__ __align__(16) __nv_bfloat16 g_woutl[960 * 384];
__device__ __align__(16) __nv_bfloat16 g_cath [NNODES * 960];
__device__ __align__(16) __nv_bfloat16 g_catl [NNODES * 960];
__device__ __align__(16) __nv_bfloat16 g_zwh  [128 * 64];
__device__ __align__(16) __nv_bfloat16 g_zwl  [128 * 64];

// ---------------- helpers ----------------
__device__ __forceinline__ void split_store(__nv_bfloat16* ph, __nv_bfloat16* pl, float x)
{
    __nv_bfloat16 h = __float2bfloat16(x);
    *ph = h;
    *pl = __float2bfloat16(x - __bfloat162float(h));
}

__device__ __forceinline__ void mma_bf16(float* c, const unsigned* a, const unsigned* b)
{
    asm volatile(
        "mma.sync.aligned.m16n8k16.row.col.f32.bf16.bf16.f32 "
        "{%0,%1,%2,%3}, {%4,%5,%6,%7}, {%8,%9}, {%0,%1,%2,%3};"
        : "+f"(c[0]), "+f"(c[1]), "+f"(c[2]), "+f"(c[3])
        : "r"(a[0]), "r"(a[1]), "r"(a[2]), "r"(a[3]), "r"(b[0]), "r"(b[1]));
}
__device__ __forceinline__ void ldsm_x4(unsigned* d, unsigned addr)
{
    asm volatile("ldmatrix.sync.aligned.m8n8.x4.shared.b16 {%0,%1,%2,%3}, [%4];"
                 : "=r"(d[0]), "=r"(d[1]), "=r"(d[2]), "=r"(d[3]) : "r"(addr));
}
__device__ __forceinline__ void ldsm_x2t(unsigned* d, unsigned addr)
{
    asm volatile("ldmatrix.sync.aligned.m8n8.x2.trans.shared.b16 {%0,%1}, [%2];"
                 : "=r"(d[0]), "=r"(d[1]) : "r"(addr));
}
__device__ __forceinline__ void cpa16(__nv_bfloat16* dst, const __nv_bfloat16* src)
{
    unsigned d = (unsigned)__cvta_generic_to_shared(dst);
    asm volatile("cp.async.ca.shared.global [%0], [%1], 16;" :: "r"(d), "l"(src));
}
#define CP_COMMIT() asm volatile("cp.async.commit_group;" ::: "memory")
#define CP_WAIT1()  asm volatile("cp.async.wait_group 1;" ::: "memory")
#define CP_WAIT0()  asm volatile("cp.async.wait_group 0;" ::: "memory")

// ---------------- prep_all ----------------
__global__ void prep_all(const float4* __restrict__ s,
                         const float* __restrict__ wq, const float* __restrict__ wkv,
                         const float* __restrict__ wqp, const float* __restrict__ wkvp,
                         const float* __restrict__ bq, const float* __restrict__ bkv,
                         const float* __restrict__ bqp, const float* __restrict__ bkvp,
                         const float* __restrict__ wout,
                         const float* __restrict__ wb, const float* __restrict__ wdz)
{
    const int t  = blockIdx.x * blockDim.x + threadIdx.x;
    const int st = gridDim.x * blockDim.x;
    for (int i = t; i < NNODES * 384 / 4; i += st) {
        float4 v = s[i];
        __nv_bfloat16* ph = g_sh + i * 4;
        __nv_bfloat16* pl = g_sl + i * 4;
        split_store(ph + 0, pl + 0, v.x);
        split_store(ph + 1, pl + 1, v.y);
        split_store(ph + 2, pl + 2, v.z);
        split_store(ph + 3, pl + 3, v.w);
    }
    for (int i = t; i < 384 * 1152; i += st) {
        int r = i / 1152, c = i % 1152;
        float v;
        if      (c < 192) v = wq  [r * 192 + c];
        else if (c < 576) v = wkv [r * 384 + (c - 192)];
        else if (c < 720) v = wqp [r * 144 + (c - 576)];
        else              v = wkvp[r * 432 + (c - 720)];
        split_store(g_wcath + i, g_wcatl + i, v);
    }
    for (int i = t; i < 960 * 384; i += st)
        split_store(g_wouth + i, g_woutl + i, wout[i]);
    for (int i = t; i < 128 * 64; i += st) {
        int r = i >> 6, c = i & 63;
        float v = 0.f;
        if      (c < 12) v = wb [r * 12 + c];
        else if (c < 44) v = wdz[r * 32 + (c - 12)];
        split_store(g_zwh + i, g_zwl + i, v);
    }
    for (int i = t; i < 1152; i += st) {
        float v;
        if      (i < 192) v = bq [i];
        else if (i < 576) v = bkv[i - 192];
        else if (i < 720) v = bqp[i - 576];
        else              v = bkvp[i - 720];
        g_bcat[i] = v;
    }
}

// ---------------- bf16 hi/lo GEMM with cp.async double-buffered stage ----------------
#define BM 128
#define BN 64
#define KC 32
#define A_E (BM * 40)         // elems per A operand per stage
#define B_E (KC * 72)         // elems per B operand per stage
#define STAGE_E (2 * A_E + 2 * B_E)            // 14848 elems
#define DYN_BYTES (2 * STAGE_E * 2)            // 59392 B (double buffer)

template<int K>
__device__ __forceinline__ void mma_gemm_ca(
    int bx, int by,
    const __nv_bfloat16* __restrict__ Ah, const __nv_bfloat16* __restrict__ Al,
    const __nv_bfloat16* __restrict__ Bh, const __nv_bfloat16* __restrict__ Bl,
    const float* __restrict__ bias, float* __restrict__ C, const int N,
    __nv_bfloat16* dyn)
{
    const int tid  = threadIdx.x;
    const int lane = tid & 31, warp = tid >> 5;
    const int wm = warp >> 2, wn = warp & 3;
    const long brow = (long)by * BM;
    const long bcol = (long)bx * BN;

    float acc[4][2][4];
#pragma unroll
    for (int mi = 0; mi < 4; mi++)
#pragma unroll
        for (int ni = 0; ni < 2; ni++)
#pragma unroll
            for (int r = 0; r < 4; r++) acc[mi][ni][r] = 0.f;

    const int arow = tid >> 1, apart = (tid & 1) * 16;
    const int bkr  = tid >> 3, bnp   = (tid & 7) * 8;

    // stage chunk kc into buffer b
    auto stage = [&](int b, int kc) {
        __nv_bfloat16* pAh = dyn + b * STAGE_E;
        __nv_bfloat16* pAl = pAh + A_E;
        __nv_bfloat16* pBh = pAh + 2 * A_E;
        __nv_bfloat16* pBl = pBh + B_E;
        const size_t aoff = (size_t)(brow + arow) * K + kc + apart;
        cpa16(pAh + arow * 40 + apart,     Ah + aoff);
        cpa16(pAh + arow * 40 + apart + 8, Ah + aoff + 8);
        cpa16(pAl + arow * 40 + apart,     Al + aoff);
        cpa16(pAl + arow * 40 + apart + 8, Al + aoff + 8);
        const size_t boff = (size_t)(kc + bkr) * N + bcol + bnp;
        cpa16(pBh + bkr * 72 + bnp, Bh + boff);
        cpa16(pBl + bkr * 72 + bnp, Bl + boff);
        CP_COMMIT();
    };

    stage(0, 0);
    int buf = 0;
    for (int kc = 0; kc < K; kc += KC) {
        const bool more = (kc + KC) < K;
        if (more) { stage(buf ^ 1, kc + KC); CP_WAIT1(); }
        else      { CP_WAIT0(); }
        __syncthreads();

        const unsigned sAh_u = (unsigned)__cvta_generic_to_shared(dyn + buf * STAGE_E);
        const unsigned sAl_u = sAh_u + A_E * 2;
        const unsigned sBh_u = sAh_u + 4 * A_E;   // bytes: 2*A_E elems later = 4*A_E? careful
        // NOTE: addresses in BYTES: sAl = sAh + A_E*2B; sBh = sAh + 2*A_E*2B; sBl = sBh + B_E*2B
        const unsigned sAl_b = sAh_u + (unsigned)(A_E * 2);
        const unsigned sBh_b = sAh_u + (unsigned)(2 * A_E * 2);
        const unsigned sBl_b = sBh_b + (unsigned)(B_E * 2);

#pragma unroll
        for (int ks = 0; ks < 2; ks++) {
            const int kk = ks * 16;
            unsigned afh[4][4], afl[4][4];
            const int g = lane >> 3, r = lane & 7;
#pragma unroll
            for (int mi = 0; mi < 4; mi++) {
                const int row = wm * 64 + mi * 16 + (g & 1) * 8 + r;
                const int col = kk + (g >> 1) * 8;
                ldsm_x4(afh[mi], sAh_u + (unsigned)(row * 40 + col) * 2u);
                ldsm_x4(afl[mi], sAl_b + (unsigned)(row * 40 + col) * 2u);
            }
            unsigned bfh[2][2], bfl[2][2];
            const int g2 = (lane >> 3) & 1, r2 = lane & 7;
#pragma unroll
            for (int ni = 0; ni < 2; ni++) {
                const int krow = kk + g2 * 8 + r2;
                const int col  = wn * 16 + ni * 8;
                ldsm_x2t(bfh[ni], sBh_b + (unsigned)(krow * 72 + col) * 2u);
                ldsm_x2t(bfl[ni], sBl_b + (unsigned)(krow * 72 + col) * 2u);
            }
#pragma unroll
            for (int mi = 0; mi < 4; mi++)
#pragma unroll
                for (int ni = 0; ni < 2; ni++) {
                    mma_bf16(acc[mi][ni], afh[mi], bfh[ni]);
                    mma_bf16(acc[mi][ni], afh[mi], bfl[ni]);
                    mma_bf16(acc[mi][ni], afl[mi], bfh[ni]);
                }
        }
        if (more) __syncthreads();
        buf ^= 1;
    }

    const int gr = lane >> 2, gc = (lane & 3) * 2;
#pragma unroll
    for (int mi = 0; mi < 4; mi++) {
        const long row0 = brow + wm * 64 + mi * 16 + gr;
#pragma unroll
        for (int ni = 0; ni < 2; ni++) {
            const long col0 = bcol + wn * 16 + ni * 8 + gc;
            const float b0 = bias[col0], b1 = bias[col0 + 1];
            float2 v0 = make_float2(acc[mi][ni][0] + b0, acc[mi][ni][1] + b1);
            float2 v1 = make_float2(acc[mi][ni][2] + b0, acc[mi][ni][3] + b1);
            *(float2*)&C[row0 * N + col0]       = v0;
            *(float2*)&C[(row0 + 8) * N + col0] = v1;
        }
    }
}

// ---------------- zproj role body (register staging; fp32->bf16 conversion) ----------------
__device__ __forceinline__ void zproj_body(
    int blk, const float* __restrict__ z,
    const float* __restrict__ bb, const float* __restrict__ bdz,
    __nv_bfloat16* sAh, __nv_bfloat16* sAl, __nv_bfloat16* sBh, __nv_bfloat16* sBl)
{
    const int tid  = threadIdx.x;
    const int lane = tid & 31, warp = tid >> 5;
    const int wm = warp >> 2, wn = warp & 3;
    const long brow = (long)blk * BM;

    float acc[4][2][4];
#pragma unroll
    for (int mi = 0; mi < 4; mi++)
#pragma unroll
        for (int ni = 0; ni < 2; ni++)
#pragma unroll
            for (int r = 0; r < 4; r++) acc[mi][ni][r] = 0.f;

    const int arow  = tid >> 1, apart = (tid & 1) * 16;
    const int bkr   = tid >> 3, bnp   = (tid & 7) * 8;

    const unsigned sAh_u = (unsigned)__cvta_generic_to_shared(sAh);
    const unsigned sAl_u = (unsigned)__cvta_generic_to_shared(sAl);
    const unsigned sBh_u = (unsigned)__cvta_generic_to_shared(sBh);
    const unsigned sBl_u = (unsigned)__cvta_generic_to_shared(sBl);

    float4 ra[4];
    uint4 rbh, rbl;
    {
        const float* ap = z + (size_t)(brow + arow) * 128 + apart;
#pragma unroll
        for (int j = 0; j < 4; j++) ra[j] = *(const float4*)(ap + j * 4);
        rbh = *(const uint4*)(g_zwh + bkr * 64 + bnp);
        rbl = *(const uint4*)(g_zwl + bkr * 64 + bnp);
    }

    for (int kc = 0; kc < 128; kc += KC) {
        __nv_bfloat16 hh[16], ll[16];
#pragma unroll
        for (int j = 0; j < 4; j++) {
            float v[4] = {ra[j].x, ra[j].y, ra[j].z, ra[j].w};
#pragma unroll
            for (int q = 0; q < 4; q++) {
                __nv_bfloat16 h = __float2bfloat16(v[q]);
                hh[j * 4 + q] = h;
                ll[j * 4 + q] = __float2bfloat16(v[q] - __bfloat162float(h));
            }
        }
        *(uint4*)(sAh + arow * 40 + apart)     = *(uint4*)hh;
        *(uint4*)(sAh + arow * 40 + apart + 8) = *(uint4*)(hh + 8);
        *(uint4*)(sAl + arow * 40 + apart)     = *(uint4*)ll;
        *(uint4*)(sAl + arow * 40 + apart + 8) = *(uint4*)(ll + 8);
        *(uint4*)(sBh + bkr * 72 + bnp) = rbh;
        *(uint4*)(sBl + bkr * 72 + bnp) = rbl;
        __syncthreads();

        const bool more = (kc + KC) < 128;
        if (more) {
            const float* ap = z + (size_t)(brow + arow) * 128 + kc + KC + apart;
#pragma unroll
            for (int j = 0; j < 4; j++) ra[j] = *(const float4*)(ap + j * 4);
            rbh = *(const uint4*)(g_zwh + (kc + KC + bkr) * 64 + bnp);
            rbl = *(const uint4*)(g_zwl + (kc + KC + bkr) * 64 + bnp);
        }

#pragma unroll
        for (int ks = 0; ks < 2; ks++) {
            const int kk = ks * 16;
            unsigned afh[4][4], afl[4][4];
            const int g = lane >> 3, r = lane & 7;
#pragma unroll
            for (int mi = 0; mi < 4; mi++) {
                const int row = wm * 64 + mi * 16 + (g & 1) * 8 + r;
                const int col = kk + (g >> 1) * 8;
                ldsm_x4(afh[mi], sAh_u + (unsigned)(row * 40 + col) * 2u);
                ldsm_x4(afl[mi], sAl_u + (unsigned)(row * 40 + col) * 2u);
            }
            unsigned bfh[2][2], bfl[2][2];
            const int g2 = (lane >> 3) & 1, r2 = lane & 7;
#pragma unroll
            for (int ni = 0; ni < 2; ni++) {
                const int krow = kk + g2 * 8 + r2;
                const int col  = wn * 16 + ni * 8;
                ldsm_x2t(bfh[ni], sBh_u + (unsigned)(krow * 72 + col) * 2u);
                ldsm_x2t(bfl[ni], sBl_u + (unsigned)(krow * 72 + col) * 2u);
            }
#pragma unroll
            for (int mi = 0; mi < 4; mi++)
#pragma unroll
                for (int ni = 0; ni < 2; ni++) {
                    mma_bf16(acc[mi][ni], afh[mi], bfh[ni]);
                    mma_bf16(acc[mi][ni], afh[mi], bfl[ni]);
                    mma_bf16(acc[mi][ni], afl[mi], bfh[ni]);
                }
        }
        if (more) __syncthreads();
    }

    const float S = 0.5773502691896258f;
    const int gr = lane >> 2, gc = (lane & 3) * 2;
#pragma unroll
    for (int mi = 0; mi < 4; mi++) {
        const long e0 = brow + wm * 64 + mi * 16 + gr;
#pragma unroll
        for (int ni = 0; ni < 2; ni++) {
            const int colb = wn * 16 + ni * 8 + gc;
#pragma unroll
            for (int r = 0; r < 4; r++) {
                const long e   = e0 + (r >> 1) * 8;
                const int  col = colb + (r & 1);
                const float v = acc[mi][ni][r];
                if (col < 12)
                    g_bpairT[(e >> 5) * 384 + col * 32 + (e & 31)] = S * (v + __ldg(bb + col));
                else if (col < 44)
                    g_pairz[e * 32 + (col - 12)] = v + __ldg(bdz + (col - 12));
            }
        }
    }
}

// ---------------- fused heavy kernel: gemm_proj (cp.async) + zproj ----------------
#define GP_BLOCKS (18 * 64)
#define ZP_BLOCKS ((NNODES * KNBR) / BM)
__global__ __launch_bounds__(256) void gz_fused(const float* __restrict__ z,
                                                const float* __restrict__ bb,
                                                const float* __restrict__ bdz)
{
    extern __shared__ __nv_bfloat16 dyn[];
    const int b = blockIdx.x;
    if (b < GP_BLOCKS) {
        mma_gemm_ca<384>(b % 18, b / 18, g_sh, g_sl, g_wcath, g_wcatl,
                         g_bcat, g_proj, 1152, dyn);
    } else {
        zproj_body(b - GP_BLOCKS, z, bb, bdz,
                   dyn, dyn + A_E, dyn + 2 * A_E, dyn + 2 * A_E + B_E);
    }
}

__global__ __launch_bounds__(256, 3) void gemm_out_mma(const float* __restrict__ bout,
                                                       float* __restrict__ out)
{
    extern __shared__ __nv_bfloat16 dyn[];
    mma_gemm_ca<960>(blockIdx.x, blockIdx.y, g_cath, g_catl, g_wouth, g_woutl,
                     bout, out, 384, dyn);
}

// ---------------- rigid transform ----------------
__global__ __launch_bounds__(192) void transform_points(const float* __restrict__ rot,
                                                        const float* __restrict__ trans)
{
    int n = blockIdx.x;
    __shared__ float R[9], T[3];
    int t = threadIdx.x;
    if (t < 9) R[t] = rot[n * 9 + t];
    if (t < 3) T[t] = trans[n * 3 + t];
    __syncthreads();
    if (t < 48) {
        const float* base = g_proj + (size_t)n * 1152 + 576;
        float x = base[t], y = base[48 + t], zz = base[96 + t];
        float* o = g_qpts + (size_t)n * 144 + t * 3;
        o[0] = fmaf(R[0], x, fmaf(R[1], y, fmaf(R[2], zz, T[0])));
        o[1] = fmaf(R[3], x, fmaf(R[4], y, fmaf(R[5], zz, T[1])));
        o[2] = fmaf(R[6], x, fmaf(R[7], y, fmaf(R[8], zz, T[2])));
    } else {
        int j = t - 48;
        const float* base = g_proj + (size_t)n * 1152 + 720;
        float x = base[j], y = base[144 + j], zz = base[288 + j];
        float* o = g_kvpts + (size_t)n * 432 + j * 3;
        o[0] = fmaf(R[0], x, fmaf(R[1], y, fmaf(R[2], zz, T[0])));
        o[1] = fmaf(R[3], x, fmaf(R[4], y, fmaf(R[5], zz, T[1])));
        o[2] = fmaf(R[6], x, fmaf(R[7], y, fmaf(R[8], zz, T[2])));
    }
}

// ---------------- fused attention (r14 proven form) ----------------
__device__ __forceinline__ void put_cat(size_t n, int idx, float v)
{
    split_store(g_cath + n * 960 + idx, g_catl + n * 960 + idx, v);
}

__global__ __launch_bounds__(384) void attn_kernel(const int* __restrict__ edge_index,
                                                   const float* __restrict__ rot,
                                                   const float* __restrict__ trans,
                                                   const float* __restrict__ mask,
                                                   const float* __restrict__ head_weights)
{
    int n = blockIdx.x;
    int t = threadIdx.x;
    __shared__ int   s_idx[32];
    __shared__ float s_mask[32];
    __shared__ float s_q[192];
    __shared__ float s_qp[144];
    __shared__ float s_R[9], s_T[3];
    __shared__ float s_hw[12];
    __shared__ float s_a[12][33];
    __shared__ float s_opt[288];
    __shared__ float s_pz[32][33];

    if (t < 32) {
        int nb = edge_index[n * 32 + t];
        s_idx[t]  = nb;
        s_mask[t] = mask[nb];
    }
    if (t >= 32 && t < 224)  s_q [t - 32]  = g_proj[(size_t)n * 1152 + (t - 32)];
    if (t >= 224 && t < 368) s_qp[t - 224] = g_qpts[(size_t)n * 144 + (t - 224)];
    if (t >= 368 && t < 377) s_R [t - 368] = rot  [n * 9 + (t - 368)];
    if (t >= 377 && t < 380) s_T [t - 377] = trans[n * 3 + (t - 377)];
    if (t < 12) {
        float x = head_weights[t];
        float sp = (x > 20.f) ? x : log1pf(expf(x));
        s_hw[t] = sp * 0.13608276348795434f;   // softplus * sqrt(1/54)
    }
    __syncthreads();

    {
        int h = t >> 5, k = t & 31;
        int nb = s_idx[k];
        const float* kg = g_proj + (size_t)nb * 1152 + 192 + h * 32;
        float dot = 0.f;
#pragma unroll
        for (int c = 0; c < 16; c++) dot = fmaf(s_q[h * 16 + c], kg[c], dot);
        const float* kp = g_kvpts + (size_t)nb * 432 + h * 36;
        float pt = 0.f;
#pragma unroll
        for (int pi = 0; pi < 12; pi++) {
            float d = s_qp[h * 12 + pi] - kp[pi];
            pt = fmaf(d, d, pt);
        }
        float logit = dot * 0.14433756729740643f
                    + g_bpairT[(size_t)n * 384 + h * 32 + k]
                    - 0.5f * s_hw[h] * pt
                    + 100000.0f * (s_mask[k] - 1.0f);
        float m = logit;
#pragma unroll
        for (int o = 16; o; o >>= 1) m = fmaxf(m, __shfl_xor_sync(0xffffffffu, m, o));
        float e = expf(logit - m);
        float ssum = e;
#pragma unroll
        for (int o = 16; o; o >>= 1) ssum += __shfl_xor_sync(0xffffffffu, ssum, o);
        s_a[h][k] = e / ssum;
    }
    for (int i = t; i < 32 * 32; i += 384)
        s_pz[i >> 5][i & 31] = g_pairz[((size_t)n * 32 + (i >> 5)) * 32 + (i & 31)];
    __syncthreads();

    if (t < 192) {
        int h = t >> 4, c = t & 15;
        float acc = 0.f;
#pragma unroll 4
        for (int k = 0; k < 32; k++)
            acc = fmaf(s_a[h][k], g_proj[(size_t)s_idx[k] * 1152 + 192 + h * 32 + 16 + c], acc);
        put_cat(n, h * 16 + c, acc);
    }
    if (t < 288) {
        int j = t / 3, i = t - j * 3;
        int h = j >> 3, p = j & 7;
        float acc = 0.f;
#pragma unroll 4
        for (int k = 0; k < 32; k++)
            acc = fmaf(s_a[h][k], g_kvpts[(size_t)s_idx[k] * 432 + h * 36 + (4 + p) * 3 + i], acc);
        s_opt[t] = acc;
    }
    {
        int h = t >> 5, c = t & 31;
        float acc = 0.f;
#pragma unroll
        for (int k = 0; k < 32; k++)
            acc = fmaf(s_a[h][k], s_pz[k][c], acc);
        put_cat(n, 576 + h * 32 + c, acc);
    }
    __syncthreads();
    if (t < 96) {
        float gx = s_opt[t * 3 + 0] - s_T[0];
        float gy = s_opt[t * 3 + 1] - s_T[1];
        float gz = s_opt[t * 3 + 2] - s_T[2];
        float lx = fmaf(s_R[0], gx, fmaf(s_R[3], gy, s_R[6] * gz));
        float ly = fmaf(s_R[1], gx, fmaf(s_R[4], gy, s_R[7] * gz));
        float lz = fmaf(s_R[2], gx, fmaf(s_R[5], gy, s_R[8] * gz));
        put_cat(n, 192 + t, lx);
        put_cat(n, 288 + t, ly);
        put_cat(n, 384 + t, lz);
        put_cat(n, 480 + t, sqrtf(fmaf(lx, lx, fmaf(ly, ly, fmaf(lz, lz, 1e-8f)))));
    }
}

// ---------------- launch ----------------
extern "C" void kernel_launch(void* const* d_in, const int* in_sizes, int n_in,
                              void* d_out, int out_size)
{
    const float* s     = (const float*)d_in[0];
    const float* z     = (const float*)d_in[1];
    const int*   ei    = (const int*)  d_in[2];
    const float* rot   = (const float*)d_in[3];
    const float* trans = (const float*)d_in[4];
    const float* mask  = (const float*)d_in[5];
    const float* w_q   = (const float*)d_in[6];
    const float* b_q   = (const float*)d_in[7];
    const float* w_kv  = (const float*)d_in[8];
    const float* b_kv  = (const float*)d_in[9];
    const float* w_qp  = (const float*)d_in[10];
    const float* b_qp  = (const float*)d_in[11];
    const float* w_kvp = (const float*)d_in[12];
    const float* b_kvp = (const float*)d_in[13];
    const float* w_b   = (const float*)d_in[14];
    const float* b_b   = (const float*)d_in[15];
    const float* w_dz  = (const float*)d_in[16];
    const float* b_dz  = (const float*)d_in[17];
    const float* hw    = (const float*)d_in[18];
    const float* w_out = (const float*)d_in[19];
    const float* b_out = (const float*)d_in[20];
    float* out = (float*)d_out;

    static bool attr_done = false;
    if (!attr_done) {
        cudaFuncSetAttribute(gz_fused, cudaFuncAttributeMaxDynamicSharedMemorySize, DYN_BYTES);
        cudaFuncSetAttribute(gemm_out_mma, cudaFuncAttributeMaxDynamicSharedMemorySize, DYN_BYTES);
        attr_done = true;
    }

    prep_all<<<512, 256>>>((const float4*)s, w_q, w_kv, w_qp, w_kvp,
                           b_q, b_kv, b_qp, b_kvp, w_out, w_b, w_dz);            // slot 1
    gz_fused<<<GP_BLOCKS + ZP_BLOCKS, 256, DYN_BYTES>>>(z, b_b, b_dz);           // slot 2
    transform_points<<<NNODES, 192>>>(rot, trans);                               // slot 3
    attn_kernel<<<NNODES, 384>>>(ei, rot, trans, mask, hw);                      // slot 4 (profiled)
    gemm_out_mma<<<dim3(384 / BN, NNODES / BM), 256, DYN_BYTES>>>(b_out, out);   // slot 5
}

// round 16
// speedup vs baseline: 1.1987x; 1.0223x over previous
#include <cuda_runtime.h>
#include <cuda_bf16.h>
#include <math.h>

#define NNODES 8192
#define KNBR   32

// ---------------- scratch (static device arrays; no allocation) ----------------
__device__ __align__(16) float g_proj  [NNODES * 1152];   // q(192)|kv(384)|qp(144)|kvp(432)
__device__ __align__(16) float g_bcat  [1152];
__device__ __align__(16) float g_qpts  [NNODES * 144];
__device__ __align__(16) float g_kvpts [NNODES * 432];
__device__ __align__(16) float g_bpairT[NNODES * 384];
__device__ __align__(16) float g_pairz [NNODES * KNBR * 32];
__device__ __align__(16) __nv_bfloat16 g_sh   [NNODES * 384];
__device__ __align__(16) __nv_bfloat16 g_sl   [NNODES * 384];
__device__ __align__(16) __nv_bfloat16 g_wcath[384 * 1152];
__device__ __align__(16) __nv_bfloat16 g_wcatl[384 * 1152];
__device__ __align__(16) __nv_bfloat16 g_wouth[960 * 384];
__device__ __align__(16) __nv_bfloat16 g_woutl[960 * 384];
__device__ __align__(16) __nv_bfloat16 g_cath [NNODES * 960];
__device__ __align__(16) __nv_bfloat16 g_catl [NNODES * 960];
__device__ __align__(16) __nv_bfloat16 g_zwh  [128 * 64];
__device__ __align__(16) __nv_bfloat16 g_zwl  [128 * 64];

// ---------------- helpers ----------------
__device__ __forceinline__ void split_store(__nv_bfloat16* ph, __nv_bfloat16* pl, float x)
{
    __nv_bfloat16 h = __float2bfloat16(x);
    *ph = h;
    *pl = __float2bfloat16(x - __bfloat162float(h));
}

__device__ __forceinline__ void mma_bf16(float* c, const unsigned* a, const unsigned* b)
{
    asm volatile(
        "mma.sync.aligned.m16n8k16.row.col.f32.bf16.bf16.f32 "
        "{%0,%1,%2,%3}, {%4,%5,%6,%7}, {%8,%9}, {%0,%1,%2,%3};"
        : "+f"(c[0]), "+f"(c[1]), "+f"(c[2]), "+f"(c[3])
        : "r"(a[0]), "r"(a[1]), "r"(a[2]), "r"(a[3]), "r"(b[0]), "r"(b[1]));
}
__device__ __forceinline__ void ldsm_x4(unsigned* d, unsigned addr)
{
    asm volatile("ldmatrix.sync.aligned.m8n8.x4.shared.b16 {%0,%1,%2,%3}, [%4];"
                 : "=r"(d[0]), "=r"(d[1]), "=r"(d[2]), "=r"(d[3]) : "r"(addr));
}
__device__ __forceinline__ void ldsm_x4t(unsigned* d, unsigned addr)
{
    asm volatile("ldmatrix.sync.aligned.m8n8.x4.trans.shared.b16 {%0,%1,%2,%3}, [%4];"
                 : "=r"(d[0]), "=r"(d[1]), "=r"(d[2]), "=r"(d[3]) : "r"(addr));
}
__device__ __forceinline__ void cpa16(__nv_bfloat16* dst, const __nv_bfloat16* src)
{
    unsigned d = (unsigned)__cvta_generic_to_shared(dst);
    asm volatile("cp.async.ca.shared.global [%0], [%1], 16;" :: "r"(d), "l"(src));
}
#define CP_COMMIT() asm volatile("cp.async.commit_group;" ::: "memory")
#define CP_WAIT1()  asm volatile("cp.async.wait_group 1;" ::: "memory")
#define CP_WAIT0()  asm volatile("cp.async.wait_group 0;" ::: "memory")

// ---------------- prep_all ----------------
__global__ void prep_all(const float4* __restrict__ s,
                         const float* __restrict__ wq, const float* __restrict__ wkv,
                         const float* __restrict__ wqp, const float* __restrict__ wkvp,
                         const float* __restrict__ bq, const float* __restrict__ bkv,
                         const float* __restrict__ bqp, const float* __restrict__ bkvp,
                         const float* __restrict__ wout,
                         const float* __restrict__ wb, const float* __restrict__ wdz)
{
    const int t  = blockIdx.x * blockDim.x + threadIdx.x;
    const int st = gridDim.x * blockDim.x;
    for (int i = t; i < NNODES * 384 / 4; i += st) {
        float4 v = s[i];
        __nv_bfloat16* ph = g_sh + i * 4;
        __nv_bfloat16* pl = g_sl + i * 4;
        split_store(ph + 0, pl + 0, v.x);
        split_store(ph + 1, pl + 1, v.y);
        split_store(ph + 2, pl + 2, v.z);
        split_store(ph + 3, pl + 3, v.w);
    }
    for (int i = t; i < 384 * 1152; i += st) {
        int r = i / 1152, c = i % 1152;
        float v;
        if      (c < 192) v = wq  [r * 192 + c];
        else if (c < 576) v = wkv [r * 384 + (c - 192)];
        else if (c < 720) v = wqp [r * 144 + (c - 576)];
        else              v = wkvp[r * 432 + (c - 720)];
        split_store(g_wcath + i, g_wcatl + i, v);
    }
    for (int i = t; i < 960 * 384; i += st)
        split_store(g_wouth + i, g_woutl + i, wout[i]);
    for (int i = t; i < 128 * 64; i += st) {
        int r = i >> 6, c = i & 63;
        float v = 0.f;
        if      (c < 12) v = wb [r * 12 + c];
        else if (c < 44) v = wdz[r * 32 + (c - 12)];
        split_store(g_zwh + i, g_zwl + i, v);
    }
    for (int i = t; i < 1152; i += st) {
        float v;
        if      (i < 192) v = bq [i];
        else if (i < 576) v = bkv[i - 192];
        else if (i < 720) v = bqp[i - 576];
        else              v = bkvp[i - 720];
        g_bcat[i] = v;
    }
}

// ---------------- bf16 hi/lo GEMM core, warp grid 4x2, B via ldsm.x4.trans ----------------
#define BM 128
#define BN 64
#define KC 32
#define A_E (BM * 40)
#define B_E (KC * 72)
#define STAGE_E (2 * A_E + 2 * B_E)
#define DYN_BYTES (2 * STAGE_E * 2)

// compute one KC chunk given smem byte-addresses; acc[2][4][4]
__device__ __forceinline__ void mma_chunk(
    float acc[2][4][4], int lane, int wm, int wn,
    unsigned sAh_b, unsigned sAl_b, unsigned sBh_b, unsigned sBl_b)
{
    const int g = lane >> 3, r = lane & 7;
    const int lb = lane & 15, cg = lane >> 4;
#pragma unroll
    for (int ks = 0; ks < 2; ks++) {
        const int kk = ks * 16;
        unsigned afh[2][4], afl[2][4];
#pragma unroll
        for (int mi = 0; mi < 2; mi++) {
            const int row = wm * 32 + mi * 16 + (g & 1) * 8 + r;
            const int col = kk + (g >> 1) * 8;
            ldsm_x4(afh[mi], sAh_b + (unsigned)(row * 40 + col) * 2u);
            ldsm_x4(afl[mi], sAl_b + (unsigned)(row * 40 + col) * 2u);
        }
        unsigned bfh[2][4], bfl[2][4];   // [pair p][4 regs]: d0,d1 = ni=2p; d2,d3 = ni=2p+1
#pragma unroll
        for (int p = 0; p < 2; p++) {
            const unsigned off = (unsigned)((kk + lb) * 72 + wn * 32 + p * 16 + cg * 8) * 2u;
            ldsm_x4t(bfh[p], sBh_b + off);
            ldsm_x4t(bfl[p], sBl_b + off);
        }
#pragma unroll
        for (int mi = 0; mi < 2; mi++)
#pragma unroll
            for (int ni = 0; ni < 4; ni++) {
                const unsigned* bh = &bfh[ni >> 1][(ni & 1) * 2];
                const unsigned* bl = &bfl[ni >> 1][(ni & 1) * 2];
                mma_bf16(acc[mi][ni], afh[mi], bh);
                mma_bf16(acc[mi][ni], afh[mi], bl);
                mma_bf16(acc[mi][ni], afl[mi], bh);
            }
    }
}

template<int K>
__device__ __forceinline__ void mma_gemm_ca(
    int bx, int by,
    const __nv_bfloat16* __restrict__ Ah, const __nv_bfloat16* __restrict__ Al,
    const __nv_bfloat16* __restrict__ Bh, const __nv_bfloat16* __restrict__ Bl,
    const float* __restrict__ bias, float* __restrict__ C, const int N,
    __nv_bfloat16* dyn)
{
    const int tid  = threadIdx.x;
    const int lane = tid & 31, warp = tid >> 5;
    const int wm = warp >> 1, wn = warp & 1;        // 4 x 2 warp grid
    const long brow = (long)by * BM;
    const long bcol = (long)bx * BN;

    float acc[2][4][4];
#pragma unroll
    for (int mi = 0; mi < 2; mi++)
#pragma unroll
        for (int ni = 0; ni < 4; ni++)
#pragma unroll
            for (int r = 0; r < 4; r++) acc[mi][ni][r] = 0.f;

    const int arow = tid >> 1, apart = (tid & 1) * 16;
    const int bkr  = tid >> 3, bnp   = (tid & 7) * 8;

    auto stage = [&](int b, int kc) {
        __nv_bfloat16* pAh = dyn + b * STAGE_E;
        __nv_bfloat16* pAl = pAh + A_E;
        __nv_bfloat16* pBh = pAh + 2 * A_E;
        __nv_bfloat16* pBl = pBh + B_E;
        const size_t aoff = (size_t)(brow + arow) * K + kc + apart;
        cpa16(pAh + arow * 40 + apart,     Ah + aoff);
        cpa16(pAh + arow * 40 + apart + 8, Ah + aoff + 8);
        cpa16(pAl + arow * 40 + apart,     Al + aoff);
        cpa16(pAl + arow * 40 + apart + 8, Al + aoff + 8);
        const size_t boff = (size_t)(kc + bkr) * N + bcol + bnp;
        cpa16(pBh + bkr * 72 + bnp, Bh + boff);
        cpa16(pBl + bkr * 72 + bnp, Bl + boff);
        CP_COMMIT();
    };

    stage(0, 0);
    int buf = 0;
    for (int kc = 0; kc < K; kc += KC) {
        const bool more = (kc + KC) < K;
        if (more) { stage(buf ^ 1, kc + KC); CP_WAIT1(); }
        else      { CP_WAIT0(); }
        __syncthreads();

        const unsigned sAh_b = (unsigned)__cvta_generic_to_shared(dyn + buf * STAGE_E);
        const unsigned sAl_b = sAh_b + (unsigned)(A_E * 2);
        const unsigned sBh_b = sAh_b + (unsigned)(2 * A_E * 2);
        const unsigned sBl_b = sBh_b + (unsigned)(B_E * 2);
        mma_chunk(acc, lane, wm, wn, sAh_b, sAl_b, sBh_b, sBl_b);

        if (more) __syncthreads();
        buf ^= 1;
    }

    const int gr = lane >> 2, gc = (lane & 3) * 2;
#pragma unroll
    for (int mi = 0; mi < 2; mi++) {
        const long row0 = brow + wm * 32 + mi * 16 + gr;
#pragma unroll
        for (int ni = 0; ni < 4; ni++) {
            const long col0 = bcol + wn * 32 + ni * 8 + gc;
            const float b0 = bias[col0], b1 = bias[col0 + 1];
            float2 v0 = make_float2(acc[mi][ni][0] + b0, acc[mi][ni][1] + b1);
            float2 v1 = make_float2(acc[mi][ni][2] + b0, acc[mi][ni][3] + b1);
            *(float2*)&C[row0 * N + col0]       = v0;
            *(float2*)&C[(row0 + 8) * N + col0] = v1;
        }
    }
}

// ---------------- zproj role body (register staging; fused fp32->bf16) ----------------
__device__ __forceinline__ void zproj_body(
    int blk, const float* __restrict__ z,
    const float* __restrict__ bb, const float* __restrict__ bdz,
    __nv_bfloat16* sAh, __nv_bfloat16* sAl, __nv_bfloat16* sBh, __nv_bfloat16* sBl)
{
    const int tid  = threadIdx.x;
    const int lane = tid & 31, warp = tid >> 5;
    const int wm = warp >> 1, wn = warp & 1;        // 4 x 2 warp grid
    const long brow = (long)blk * BM;

    float acc[2][4][4];
#pragma unroll
    for (int mi = 0; mi < 2; mi++)
#pragma unroll
        for (int ni = 0; ni < 4; ni++)
#pragma unroll
            for (int r = 0; r < 4; r++) acc[mi][ni][r] = 0.f;

    const int arow  = tid >> 1, apart = (tid & 1) * 16;
    const int bkr   = tid >> 3, bnp   = (tid & 7) * 8;

    const unsigned sAh_b = (unsigned)__cvta_generic_to_shared(sAh);
    const unsigned sAl_b = (unsigned)__cvta_generic_to_shared(sAl);
    const unsigned sBh_b = (unsigned)__cvta_generic_to_shared(sBh);
    const unsigned sBl_b = (unsigned)__cvta_generic_to_shared(sBl);

    float4 ra[4];
    uint4 rbh, rbl;
    {
        const float* ap = z + (size_t)(brow + arow) * 128 + apart;
#pragma unroll
        for (int j = 0; j < 4; j++) ra[j] = *(const float4*)(ap + j * 4);
        rbh = *(const uint4*)(g_zwh + bkr * 64 + bnp);
        rbl = *(const uint4*)(g_zwl + bkr * 64 + bnp);
    }

    for (int kc = 0; kc < 128; kc += KC) {
        __nv_bfloat16 hh[16], ll[16];
#pragma unroll
        for (int j = 0; j < 4; j++) {
            float v[4] = {ra[j].x, ra[j].y, ra[j].z, ra[j].w};
#pragma unroll
            for (int q = 0; q < 4; q++) {
                __nv_bfloat16 h = __float2bfloat16(v[q]);
                hh[j * 4 + q] = h;
                ll[j * 4 + q] = __float2bfloat16(v[q] - __bfloat162float(h));
            }
        }
        *(uint4*)(sAh + arow * 40 + apart)     = *(uint4*)hh;
        *(uint4*)(sAh + arow * 40 + apart + 8) = *(uint4*)(hh + 8);
        *(uint4*)(sAl + arow * 40 + apart)     = *(uint4*)ll;
        *(uint4*)(sAl + arow * 40 + apart + 8) = *(uint4*)(ll + 8);
        *(uint4*)(sBh + bkr * 72 + bnp) = rbh;
        *(uint4*)(sBl + bkr * 72 + bnp) = rbl;
        __syncthreads();

        const bool more = (kc + KC) < 128;
        if (more) {
            const float* ap = z + (size_t)(brow + arow) * 128 + kc + KC + apart;
#pragma unroll
            for (int j = 0; j < 4; j++) ra[j] = *(const float4*)(ap + j * 4);
            rbh = *(const uint4*)(g_zwh + (kc + KC + bkr) * 64 + bnp);
            rbl = *(const uint4*)(g_zwl + (kc + KC + bkr) * 64 + bnp);
        }

        mma_chunk(acc, lane, wm, wn, sAh_b, sAl_b, sBh_b, sBl_b);
        if (more) __syncthreads();
    }

    const float S = 0.5773502691896258f;
    const int gr = lane >> 2, gc = (lane & 3) * 2;
#pragma unroll
    for (int mi = 0; mi < 2; mi++) {
        const long e0 = brow + wm * 32 + mi * 16 + gr;
#pragma unroll
        for (int ni = 0; ni < 4; ni++) {
            const int colb = wn * 32 + ni * 8 + gc;
#pragma unroll
            for (int r = 0; r < 4; r++) {
                const long e   = e0 + (r >> 1) * 8;
                const int  col = colb + (r & 1);
                const float v = acc[mi][ni][r];
                if (col < 12)
                    g_bpairT[(e >> 5) * 384 + col * 32 + (e & 31)] = S * (v + __ldg(bb + col));
                else if (col < 44)
                    g_pairz[e * 32 + (col - 12)] = v + __ldg(bdz + (col - 12));
            }
        }
    }
}

// ---------------- fused heavy kernel ----------------
#define GP_BLOCKS (18 * 64)
#define ZP_BLOCKS ((NNODES * KNBR) / BM)
__global__ __launch_bounds__(256) void gz_fused(const float* __restrict__ z,
                                                const float* __restrict__ bb,
                                                const float* __restrict__ bdz)
{
    extern __shared__ __nv_bfloat16 dyn[];
    const int b = blockIdx.x;
    if (b < GP_BLOCKS) {
        mma_gemm_ca<384>(b % 18, b / 18, g_sh, g_sl, g_wcath, g_wcatl,
                         g_bcat, g_proj, 1152, dyn);
    } else {
        zproj_body(b - GP_BLOCKS, z, bb, bdz,
                   dyn, dyn + A_E, dyn + 2 * A_E, dyn + 2 * A_E + B_E);
    }
}

__global__ __launch_bounds__(256, 3) void gemm_out_mma(const float* __restrict__ bout,
                                                       float* __restrict__ out)
{
    extern __shared__ __nv_bfloat16 dyn[];
    mma_gemm_ca<960>(blockIdx.x, blockIdx.y, g_cath, g_catl, g_wouth, g_woutl,
                     bout, out, 384, dyn);
}

// ---------------- rigid transform ----------------
__global__ __launch_bounds__(192) void transform_points(const float* __restrict__ rot,
                                                        const float* __restrict__ trans)
{
    int n = blockIdx.x;
    __shared__ float R[9], T[3];
    int t = threadIdx.x;
    if (t < 9) R[t] = rot[n * 9 + t];
    if (t < 3) T[t] = trans[n * 3 + t];
    __syncthreads();
    if (t < 48) {
        const float* base = g_proj + (size_t)n * 1152 + 576;
        float x = base[t], y = base[48 + t], zz = base[96 + t];
        float* o = g_qpts + (size_t)n * 144 + t * 3;
        o[0] = fmaf(R[0], x, fmaf(R[1], y, fmaf(R[2], zz, T[0])));
        o[1] = fmaf(R[3], x, fmaf(R[4], y, fmaf(R[5], zz, T[1])));
        o[2] = fmaf(R[6], x, fmaf(R[7], y, fmaf(R[8], zz, T[2])));
    } else {
        int j = t - 48;
        const float* base = g_proj + (size_t)n * 1152 + 720;
        float x = base[j], y = base[144 + j], zz = base[288 + j];
        float* o = g_kvpts + (size_t)n * 432 + j * 3;
        o[0] = fmaf(R[0], x, fmaf(R[1], y, fmaf(R[2], zz, T[0])));
        o[1] = fmaf(R[3], x, fmaf(R[4], y, fmaf(R[5], zz, T[1])));
        o[2] = fmaf(R[6], x, fmaf(R[7], y, fmaf(R[8], zz, T[2])));
    }
}

// ---------------- fused attention (proven r14/r15 form) ----------------
__device__ __forceinline__ void put_cat(size_t n, int idx, float v)
{
    split_store(g_cath + n * 960 + idx, g_catl + n * 960 + idx, v);
}

__global__ __launch_bounds__(384) void attn_kernel(const int* __restrict__ edge_index,
                                                   const float* __restrict__ rot,
                                                   const float* __restrict__ trans,
                                                   const float* __restrict__ mask,
                                                   const float* __restrict__ head_weights)
{
    int n = blockIdx.x;
    int t = threadIdx.x;
    __shared__ int   s_idx[32];
    __shared__ float s_mask[32];
    __shared__ float s_q[192];
    __shared__ float s_qp[144];
    __shared__ float s_R[9], s_T[3];
    __shared__ float s_hw[12];
    __shared__ float s_a[12][33];
    __shared__ float s_opt[288];
    __shared__ float s_pz[32][33];

    if (t < 32) {
        int nb = edge_index[n * 32 + t];
        s_idx[t]  = nb;
        s_mask[t] = mask[nb];
    }
    if (t >= 32 && t < 224)  s_q [t - 32]  = g_proj[(size_t)n * 1152 + (t - 32)];
    if (t >= 224 && t < 368) s_qp[t - 224] = g_qpts[(size_t)n * 144 + (t - 224)];
    if (t >= 368 && t < 377) s_R [t - 368] = rot  [n * 9 + (t - 368)];
    if (t >= 377 && t < 380) s_T [t - 377] = trans[n * 3 + (t - 377)];
    if (t < 12) {
        float x = head_weights[t];
        float sp = (x > 20.f) ? x : log1pf(expf(x));
        s_hw[t] = sp * 0.13608276348795434f;   // softplus * sqrt(1/54)
    }
    __syncthreads();

    {
        int h = t >> 5, k = t & 31;
        int nb = s_idx[k];
        const float* kg = g_proj + (size_t)nb * 1152 + 192 + h * 32;
        float dot = 0.f;
#pragma unroll
        for (int c = 0; c < 16; c++) dot = fmaf(s_q[h * 16 + c], kg[c], dot);
        const float* kp = g_kvpts + (size_t)nb * 432 + h * 36;
        float pt = 0.f;
#pragma unroll
        for (int pi = 0; pi < 12; pi++) {
            float d = s_qp[h * 12 + pi] - kp[pi];
            pt = fmaf(d, d, pt);
        }
        float logit = dot * 0.14433756729740643f
                    + g_bpairT[(size_t)n * 384 + h * 32 + k]
                    - 0.5f * s_hw[h] * pt
                    + 100000.0f * (s_mask[k] - 1.0f);
        float m = logit;
#pragma unroll
        for (int o = 16; o; o >>= 1) m = fmaxf(m, __shfl_xor_sync(0xffffffffu, m, o));
        float e = expf(logit - m);
        float ssum = e;
#pragma unroll
        for (int o = 16; o; o >>= 1) ssum += __shfl_xor_sync(0xffffffffu, ssum, o);
        s_a[h][k] = e / ssum;
    }
    for (int i = t; i < 32 * 32; i += 384)
        s_pz[i >> 5][i & 31] = g_pairz[((size_t)n * 32 + (i >> 5)) * 32 + (i & 31)];
    __syncthreads();

    if (t < 192) {
        int h = t >> 4, c = t & 15;
        float acc = 0.f;
#pragma unroll 4
        for (int k = 0; k < 32; k++)
            acc = fmaf(s_a[h][k], g_proj[(size_t)s_idx[k] * 1152 + 192 + h * 32 + 16 + c], acc);
        put_cat(n, h * 16 + c, acc);
    }
    if (t < 288) {
        int j = t / 3, i = t - j * 3;
        int h = j >> 3, p = j & 7;
        float acc = 0.f;
#pragma unroll 4
        for (int k = 0; k < 32; k++)
            acc = fmaf(s_a[h][k], g_kvpts[(size_t)s_idx[k] * 432 + h * 36 + (4 + p) * 3 + i], acc);
        s_opt[t] = acc;
    }
    {
        int h = t >> 5, c = t & 31;
        float acc = 0.f;
#pragma unroll
        for (int k = 0; k < 32; k++)
            acc = fmaf(s_a[h][k], s_pz[k][c], acc);
        put_cat(n, 576 + h * 32 + c, acc);
    }
    __syncthreads();
    if (t < 96) {
        float gx = s_opt[t * 3 + 0] - s_T[0];
        float gy = s_opt[t * 3 + 1] - s_T[1];
        float gz = s_opt[t * 3 + 2] - s_T[2];
        float lx = fmaf(s_R[0], gx, fmaf(s_R[3], gy, s_R[6] * gz));
        float ly = fmaf(s_R[1], gx, fmaf(s_R[4], gy, s_R[7] * gz));
        float lz = fmaf(s_R[2], gx, fmaf(s_R[5], gy, s_R[8] * gz));
        put_cat(n, 192 + t, lx);
        put_cat(n, 288 + t, ly);
        put_cat(n, 384 + t, lz);
        put_cat(n, 480 + t, sqrtf(fmaf(lx, lx, fmaf(ly, ly, fmaf(lz, lz, 1e-8f)))));
    }
}

// ---------------- launch ----------------
extern "C" void kernel_launch(void* const* d_in, const int* in_sizes, int n_in,
                              void* d_out, int out_size)
{
    const float* s     = (const float*)d_in[0];
    const float* z     = (const float*)d_in[1];
    const int*   ei    = (const int*)  d_in[2];
    const float* rot   = (const float*)d_in[3];
    const float* trans = (const float*)d_in[4];
    const float* mask  = (const float*)d_in[5];
    const float* w_q   = (const float*)d_in[6];
    const float* b_q   = (const float*)d_in[7];
    const float* w_kv  = (const float*)d_in[8];
    const float* b_kv  = (const float*)d_in[9];
    const float* w_qp  = (const float*)d_in[10];
    const float* b_qp  = (const float*)d_in[11];
    const float* w_kvp = (const float*)d_in[12];
    const float* b_kvp = (const float*)d_in[13];
    const float* w_b   = (const float*)d_in[14];
    const float* b_b   = (const float*)d_in[15];
    const float* w_dz  = (const float*)d_in[16];
    const float* b_dz  = (const float*)d_in[17];
    const float* hw    = (const float*)d_in[18];
    const float* w_out = (const float*)d_in[19];
    const float* b_out = (const float*)d_in[20];
    float* out = (float*)d_out;

    static bool attr_done = false;
    if (!attr_done) {
        cudaFuncSetAttribute(gz_fused, cudaFuncAttributeMaxDynamicSharedMemorySize, DYN_BYTES);
        cudaFuncSetAttribute(gemm_out_mma, cudaFuncAttributeMaxDynamicSharedMemorySize, DYN_BYTES);
        attr_done = true;
    }

    prep_all<<<512, 256>>>((const float4*)s, w_q, w_kv, w_qp, w_kvp,
                           b_q, b_kv, b_qp, b_kvp, w_out, w_b, w_dz);            // slot 1
    gz_fused<<<GP_BLOCKS + ZP_BLOCKS, 256, DYN_BYTES>>>(z, b_b, b_dz);           // slot 2
    transform_points<<<NNODES, 192>>>(rot, trans);                               // slot 3
    attn_kernel<<<NNODES, 384>>>(ei, rot, trans, mask, hw);                      // slot 4 (profiled)
    gemm_out_mma<<<dim3(384 / BN, NNODES / BM), 256, DYN_BYTES>>>(b_out, out);   // slot 5
}